// round 4
// baseline (speedup 1.0000x reference)
#include <cuda_runtime.h>
#include <cuda_bf16.h>

#define NEMB 1024
#define HS 64
#define BB 8
#define TT 2048
#define BT (BB*TT)
#define LDB 72          // smem row stride in bf16 (144B: conflict-free ldmatrix)
#define NQT (TT/64)     // 32 query tiles per batch

__device__ __align__(16) __nv_bfloat16 gQh[BT*HS];
__device__ __align__(16) __nv_bfloat16 gQl[BT*HS];
__device__ __align__(16) __nv_bfloat16 gKh[BT*HS];
__device__ __align__(16) __nv_bfloat16 gKl[BT*HS];
__device__ __align__(16) __nv_bfloat16 gVh[BT*HS];
__device__ __align__(16) __nv_bfloat16 gVl[BT*HS];
// pre-split weights (3 mats x NEMB x HS)
__device__ __align__(16) __nv_bfloat16 gWh3[3*NEMB*HS];
__device__ __align__(16) __nv_bfloat16 gWl3[3*NEMB*HS];

__device__ __forceinline__ unsigned su32(const void* p) {
    return (unsigned)__cvta_generic_to_shared(p);
}
__device__ __forceinline__ void ldsm4(unsigned a, unsigned* r) {
    asm volatile("ldmatrix.sync.aligned.m8n8.x4.shared.b16 {%0,%1,%2,%3},[%4];\n"
                 : "=r"(r[0]), "=r"(r[1]), "=r"(r[2]), "=r"(r[3]) : "r"(a));
}
__device__ __forceinline__ void ldsm4t(unsigned a, unsigned* r) {
    asm volatile("ldmatrix.sync.aligned.m8n8.x4.trans.shared.b16 {%0,%1,%2,%3},[%4];\n"
                 : "=r"(r[0]), "=r"(r[1]), "=r"(r[2]), "=r"(r[3]) : "r"(a));
}
__device__ __forceinline__ void mma16816(float* c, const unsigned* a, unsigned b0, unsigned b1) {
    asm volatile("mma.sync.aligned.m16n8k16.row.col.f32.bf16.bf16.f32 "
                 "{%0,%1,%2,%3},{%4,%5,%6,%7},{%8,%9},{%0,%1,%2,%3};\n"
                 : "+f"(c[0]), "+f"(c[1]), "+f"(c[2]), "+f"(c[3])
                 : "r"(a[0]), "r"(a[1]), "r"(a[2]), "r"(a[3]), "r"(b0), "r"(b1));
}
__device__ __forceinline__ void splitp(float x, float y, unsigned& h, unsigned& l) {
    __nv_bfloat162 hh = __floats2bfloat162_rn(x, y);
    float2 f = __bfloat1622float2(hh);
    __nv_bfloat162 ll = __floats2bfloat162_rn(x - f.x, y - f.y);
    h = *(unsigned*)&hh; l = *(unsigned*)&ll;
}
__device__ __forceinline__ void split4s(float4 v, __nv_bfloat16* dh, __nv_bfloat16* dl) {
    unsigned h0, l0, h1, l1;
    splitp(v.x, v.y, h0, l0); splitp(v.z, v.w, h1, l1);
    *(uint2*)dh = make_uint2(h0, h1);
    *(uint2*)dl = make_uint2(l0, l1);
}

// ---------------------------------------------------------------------------
// Pre-split weights into bf16 hi/lo (once; tiny).
// ---------------------------------------------------------------------------
__global__ void splitw_kernel(const float* __restrict__ Wq,
                              const float* __restrict__ Wk,
                              const float* __restrict__ Wv)
{
    const float* Wsrc[3] = {Wq, Wk, Wv};
    int u = blockIdx.x * 256 + threadIdx.x;          // one float4 per thread
    int mat = u >> 14;                               // 16384 float4 per mat
    int off = (u & 16383) * 4;
    float4 v = *(const float4*)&Wsrc[mat][off];
    split4s(v, &gWh3[mat*NEMB*HS + off], &gWl3[mat*NEMB*HS + off]);
}

// ---------------------------------------------------------------------------
// Projection: one CTA = 64 rows of X -> Q,K,V (bf16x3 MMA), hi/lo outputs.
// 8 warps: 4 m-groups x 2 n-groups(32 cols).
// ---------------------------------------------------------------------------
__global__ __launch_bounds__(256) void proj_kernel(const float* __restrict__ x)
{
    extern __shared__ char smc[];
    __nv_bfloat16* sXh = (__nv_bfloat16*)smc;       // 64*LDB
    __nv_bfloat16* sXl = sXh + 64*LDB;
    __nv_bfloat16* sWh = sXl + 64*LDB;              // 3 mats x 64*LDB
    __nv_bfloat16* sWl = sWh + 3*64*LDB;

    const int bt0 = blockIdx.x * 64;
    const int tid = threadIdx.x, lane = tid & 31, wid = tid >> 5;
    const int wm = wid & 3, wn = wid >> 2;

    float acc[3][4][4];
    #pragma unroll
    for (int m = 0; m < 3; ++m)
        #pragma unroll
        for (int t = 0; t < 4; ++t)
            #pragma unroll
            for (int r = 0; r < 4; ++r) acc[m][t][r] = 0.f;

    for (int kt = 0; kt < NEMB/64; ++kt) {
        __syncthreads();
        // X tile 64x64: split fp32 -> hi/lo
        #pragma unroll
        for (int r = 0; r < 4; ++r) {
            int u = tid + 256*r, row = u >> 4, c = (u & 15) * 4;
            float4 v = *(const float4*)&x[(size_t)(bt0+row)*NEMB + kt*64 + c];
            split4s(v, &sXh[row*LDB+c], &sXl[row*LDB+c]);
        }
        // W tiles: already bf16 hi/lo in global. 1536 uint4 each.
        #pragma unroll
        for (int r = 0; r < 6; ++r) {
            int u = tid + 256*r;
            int mat = u >> 9, rem = u & 511;
            int row = rem >> 3, c = (rem & 7) * 8;
            size_t g = (size_t)mat*NEMB*HS + (size_t)(kt*64+row)*HS + c;
            int s = mat*64*LDB + row*LDB + c;
            *(uint4*)&sWh[s] = *(const uint4*)&gWh3[g];
            *(uint4*)&sWl[s] = *(const uint4*)&gWl3[g];
        }
        __syncthreads();

        #pragma unroll
        for (int kk = 0; kk < 4; ++kk) {
            unsigned ah[4], al[4];
            unsigned ao = (unsigned)(((wm*16 + (lane&15))*LDB + kk*16 + (lane>>4)*8) * 2);
            ldsm4(su32(sXh) + ao, ah);
            ldsm4(su32(sXl) + ao, al);
            #pragma unroll
            for (int mat = 0; mat < 3; ++mat) {
                #pragma unroll
                for (int nb = 0; nb < 2; ++nb) {
                    unsigned bh[4], bl[4];
                    unsigned bo = (unsigned)((mat*64*LDB + (kk*16 + (lane&15))*LDB +
                                              wn*32 + nb*16 + (lane>>4)*8) * 2);
                    ldsm4t(su32(sWh) + bo, bh);
                    ldsm4t(su32(sWl) + bo, bl);
                    float* c0 = acc[mat][nb*2]; float* c1 = acc[mat][nb*2+1];
                    mma16816(c0, ah, bh[0], bh[1]);
                    mma16816(c0, ah, bl[0], bl[1]);
                    mma16816(c0, al, bh[0], bh[1]);
                    mma16816(c1, ah, bh[2], bh[3]);
                    mma16816(c1, ah, bl[2], bl[3]);
                    mma16816(c1, al, bh[2], bh[3]);
                }
            }
        }
    }

    __nv_bfloat16* const GH[3] = {gQh, gKh, gVh};
    __nv_bfloat16* const GL[3] = {gQl, gKl, gVl};
    const int r0 = bt0 + wm*16 + (lane >> 2);
    #pragma unroll
    for (int mat = 0; mat < 3; ++mat)
        #pragma unroll
        for (int nt = 0; nt < 4; ++nt) {
            int col = wn*32 + nt*8 + 2*(lane & 3);
            unsigned h, l;
            splitp(acc[mat][nt][0], acc[mat][nt][1], h, l);
            *(unsigned*)&GH[mat][(size_t)r0*HS + col] = h;
            *(unsigned*)&GL[mat][(size_t)r0*HS + col] = l;
            splitp(acc[mat][nt][2], acc[mat][nt][3], h, l);
            *(unsigned*)&GH[mat][(size_t)(r0+8)*HS + col] = h;
            *(unsigned*)&GL[mat][(size_t)(r0+8)*HS + col] = l;
        }
}

// ---------------------------------------------------------------------------
// Flash attention, bf16x3 MMA. One CTA per (batch, query tile); heavy tiles
// launch first; 3 CTAs resident per SM. 4 warps; warp w owns rows w*16..+15.
// ---------------------------------------------------------------------------
__global__ __launch_bounds__(128, 3) void attn_kernel(float* __restrict__ out)
{
    extern __shared__ char smc[];
    __nv_bfloat16* sQh = (__nv_bfloat16*)smc;
    __nv_bfloat16* sQl = sQh + 64*LDB;
    __nv_bfloat16* sKh = sQl + 64*LDB;
    __nv_bfloat16* sKl = sKh + 64*LDB;
    __nv_bfloat16* sVh = sKl + 64*LDB;
    __nv_bfloat16* sVl = sVh + 64*LDB;

    const int b = blockIdx.y;
    const int qt = NQT - 1 - blockIdx.x;   // heavy tiles first
    const int t0 = qt * 64;
    const int tid = threadIdx.x, lane = tid & 31, w = tid >> 5;
    const int lr = lane >> 2;
    const int lc2 = 2 * (lane & 3);

    // load Q tile hi/lo
    #pragma unroll
    for (int r = 0; r < 4; ++r) {
        int u = tid + 128*r, row = u >> 3, c = (u & 7) * 8;
        size_t g = (size_t)(b*TT + t0 + row) * HS + c;
        *(uint4*)&sQh[row*LDB + c] = *(const uint4*)&gQh[g];
        *(uint4*)&sQl[row*LDB + c] = *(const uint4*)&gQl[g];
    }
    __syncthreads();
    unsigned qh[4][4], ql[4][4];
    #pragma unroll
    for (int kk = 0; kk < 4; ++kk) {
        unsigned ao = (unsigned)(((w*16 + (lane&15))*LDB + kk*16 + (lane>>4)*8) * 2);
        ldsm4(su32(sQh) + ao, qh[kk]);
        ldsm4(su32(sQl) + ao, ql[kk]);
    }

    float o[8][4];
    #pragma unroll
    for (int t = 0; t < 8; ++t)
        #pragma unroll
        for (int r = 0; r < 4; ++r) o[t][r] = 0.f;
    float m0 = -1e30f, m1 = -1e30f, l0 = 0.f, l1 = 0.f;

    for (int kt = 0; kt <= qt; ++kt) {
        __syncthreads();
        #pragma unroll
        for (int r = 0; r < 4; ++r) {
            int u = tid + 128*r, row = u >> 3, c = (u & 7) * 8;
            size_t g = (size_t)(b*TT + kt*64 + row) * HS + c;
            int s = row*LDB + c;
            *(uint4*)&sKh[s] = *(const uint4*)&gKh[g];
            *(uint4*)&sKl[s] = *(const uint4*)&gKl[g];
            *(uint4*)&sVh[s] = *(const uint4*)&gVh[g];
            *(uint4*)&sVl[s] = *(const uint4*)&gVl[g];
        }
        __syncthreads();

        // S = Q K^T (bf16x3)
        float st[8][4];
        #pragma unroll
        for (int t = 0; t < 8; ++t)
            #pragma unroll
            for (int r = 0; r < 4; ++r) st[t][r] = 0.f;
        #pragma unroll
        for (int kk = 0; kk < 4; ++kk) {
            #pragma unroll
            for (int kb = 0; kb < 4; ++kb) {
                unsigned kh[4], kl[4];
                unsigned ko = (unsigned)(((kb*16 + (lane&15))*LDB + kk*16 + (lane>>4)*8) * 2);
                ldsm4(su32(sKh) + ko, kh);
                ldsm4(su32(sKl) + ko, kl);
                float* c0 = st[kb*2]; float* c1 = st[kb*2+1];
                mma16816(c0, qh[kk], kh[0], kh[2]);
                mma16816(c0, qh[kk], kl[0], kl[2]);
                mma16816(c0, ql[kk], kh[0], kh[2]);
                mma16816(c1, qh[kk], kh[1], kh[3]);
                mma16816(c1, qh[kk], kl[1], kl[3]);
                mma16816(c1, ql[kk], kh[1], kh[3]);
            }
        }

        if (kt == qt) {
            int r0 = w*16 + lr, r1 = r0 + 8;
            #pragma unroll
            for (int nt = 0; nt < 8; ++nt) {
                int c = nt*8 + lc2;
                if (c     > r0) st[nt][0] = -1e30f;
                if (c + 1 > r0) st[nt][1] = -1e30f;
                if (c     > r1) st[nt][2] = -1e30f;
                if (c + 1 > r1) st[nt][3] = -1e30f;
            }
        }

        // online softmax
        float mx0 = -1e30f, mx1 = -1e30f;
        #pragma unroll
        for (int nt = 0; nt < 8; ++nt) {
            mx0 = fmaxf(mx0, fmaxf(st[nt][0], st[nt][1]));
            mx1 = fmaxf(mx1, fmaxf(st[nt][2], st[nt][3]));
        }
        mx0 = fmaxf(mx0, __shfl_xor_sync(0xffffffffu, mx0, 1));
        mx0 = fmaxf(mx0, __shfl_xor_sync(0xffffffffu, mx0, 2));
        mx1 = fmaxf(mx1, __shfl_xor_sync(0xffffffffu, mx1, 1));
        mx1 = fmaxf(mx1, __shfl_xor_sync(0xffffffffu, mx1, 2));
        float mn0 = fmaxf(m0, mx0), mn1 = fmaxf(m1, mx1);
        float a0 = __expf(m0 - mn0), a1 = __expf(m1 - mn1);
        float s0 = 0.f, s1 = 0.f;
        #pragma unroll
        for (int nt = 0; nt < 8; ++nt) {
            st[nt][0] = __expf(st[nt][0] - mn0);
            st[nt][1] = __expf(st[nt][1] - mn0);
            st[nt][2] = __expf(st[nt][2] - mn1);
            st[nt][3] = __expf(st[nt][3] - mn1);
            s0 += st[nt][0] + st[nt][1];
            s1 += st[nt][2] + st[nt][3];
        }
        s0 += __shfl_xor_sync(0xffffffffu, s0, 1);
        s0 += __shfl_xor_sync(0xffffffffu, s0, 2);
        s1 += __shfl_xor_sync(0xffffffffu, s1, 1);
        s1 += __shfl_xor_sync(0xffffffffu, s1, 2);
        l0 = l0 * a0 + s0; l1 = l1 * a1 + s1;
        m0 = mn0; m1 = mn1;
        #pragma unroll
        for (int nt = 0; nt < 8; ++nt) {
            o[nt][0] *= a0; o[nt][1] *= a0; o[nt][2] *= a1; o[nt][3] *= a1;
        }

        // P fragments (register repack)
        unsigned ph[4][4], pl[4][4];
        #pragma unroll
        for (int t = 0; t < 4; ++t) {
            splitp(st[2*t][0],   st[2*t][1],   ph[t][0], pl[t][0]);
            splitp(st[2*t][2],   st[2*t][3],   ph[t][1], pl[t][1]);
            splitp(st[2*t+1][0], st[2*t+1][1], ph[t][2], pl[t][2]);
            splitp(st[2*t+1][2], st[2*t+1][3], ph[t][3], pl[t][3]);
        }
        // O += P V (bf16x3)
        #pragma unroll
        for (int t = 0; t < 4; ++t) {
            #pragma unroll
            for (int nb = 0; nb < 4; ++nb) {
                unsigned vh[4], vl[4];
                unsigned vo = (unsigned)(((t*16 + (lane&15))*LDB + nb*16 + (lane>>4)*8) * 2);
                ldsm4t(su32(sVh) + vo, vh);
                ldsm4t(su32(sVl) + vo, vl);
                float* c0 = o[nb*2]; float* c1 = o[nb*2+1];
                mma16816(c0, ph[t], vh[0], vh[1]);
                mma16816(c0, ph[t], vl[0], vl[1]);
                mma16816(c0, pl[t], vh[0], vh[1]);
                mma16816(c1, ph[t], vh[2], vh[3]);
                mma16816(c1, ph[t], vl[2], vl[3]);
                mma16816(c1, pl[t], vh[2], vh[3]);
            }
        }
    }

    // epilogue
    float i0 = 1.f / l0, i1 = 1.f / l1;
    int gr0 = b*TT + t0 + w*16 + lr;
    #pragma unroll
    for (int nt = 0; nt < 8; ++nt) {
        int col = nt*8 + lc2;
        *(float2*)&out[(size_t)gr0*HS + col]     = make_float2(o[nt][0]*i0, o[nt][1]*i0);
        *(float2*)&out[(size_t)(gr0+8)*HS + col] = make_float2(o[nt][2]*i1, o[nt][3]*i1);
    }
}

// ---------------------------------------------------------------------------
static const int PROJ_SMEM = 8 * 64 * LDB * 2;   // 73728
static const int ATTN_SMEM = 6 * 64 * LDB * 2;   // 55296

extern "C" void kernel_launch(void* const* d_in, const int* in_sizes, int n_in,
                              void* d_out, int out_size)
{
    const float* x  = (const float*)d_in[0];
    const float* Wq = (const float*)d_in[1];
    const float* Wk = (const float*)d_in[2];
    const float* Wv = (const float*)d_in[3];
    float* out = (float*)d_out;
    (void)in_sizes; (void)n_in; (void)out_size;

    cudaFuncSetAttribute(proj_kernel, cudaFuncAttributeMaxDynamicSharedMemorySize, PROJ_SMEM);
    cudaFuncSetAttribute(attn_kernel, cudaFuncAttributeMaxDynamicSharedMemorySize, ATTN_SMEM);

    splitw_kernel<<<3*NEMB*HS/1024, 256>>>(Wq, Wk, Wv);
    proj_kernel<<<BT/64, 256, PROJ_SMEM>>>(x);
    attn_kernel<<<dim3(NQT, BB), 128, ATTN_SMEM>>>(out);
}

// round 5
// speedup vs baseline: 1.2574x; 1.2574x over previous
#include <cuda_runtime.h>
#include <cuda_bf16.h>

#define NEMB 1024
#define HS 64
#define BB 8
#define TT 2048
#define BT (BB*TT)
#define LDB 72          // smem row stride in bf16 (144B: conflict-free ldmatrix)
#define NQT (TT/64)     // 32 query tiles per batch
#define CHK 8           // key-tiles per split-K chunk
#define MAXC 4          // max chunks per query tile

__device__ __align__(16) __nv_bfloat16 gQh[BT*HS];
__device__ __align__(16) __nv_bfloat16 gQl[BT*HS];
__device__ __align__(16) __nv_bfloat16 gKh[BT*HS];
__device__ __align__(16) __nv_bfloat16 gKl[BT*HS];
__device__ __align__(16) __nv_bfloat16 gVh[BT*HS];
__device__ __align__(16) __nv_bfloat16 gVl[BT*HS];
__device__ __align__(16) __nv_bfloat16 gWh3[3*NEMB*HS];
__device__ __align__(16) __nv_bfloat16 gWl3[3*NEMB*HS];
// split-K partials: O unnormalized + per-row m,l
__device__ __align__(16) float gOp[BB*NQT*MAXC*64*HS];
__device__ float gM[BB*NQT*MAXC*64];
__device__ float gL[BB*NQT*MAXC*64];

__device__ __forceinline__ unsigned su32(const void* p) {
    return (unsigned)__cvta_generic_to_shared(p);
}
__device__ __forceinline__ void ldsm4(unsigned a, unsigned* r) {
    asm volatile("ldmatrix.sync.aligned.m8n8.x4.shared.b16 {%0,%1,%2,%3},[%4];\n"
                 : "=r"(r[0]), "=r"(r[1]), "=r"(r[2]), "=r"(r[3]) : "r"(a));
}
__device__ __forceinline__ void ldsm4t(unsigned a, unsigned* r) {
    asm volatile("ldmatrix.sync.aligned.m8n8.x4.trans.shared.b16 {%0,%1,%2,%3},[%4];\n"
                 : "=r"(r[0]), "=r"(r[1]), "=r"(r[2]), "=r"(r[3]) : "r"(a));
}
__device__ __forceinline__ void mma16816(float* c, const unsigned* a, unsigned b0, unsigned b1) {
    asm volatile("mma.sync.aligned.m16n8k16.row.col.f32.bf16.bf16.f32 "
                 "{%0,%1,%2,%3},{%4,%5,%6,%7},{%8,%9},{%0,%1,%2,%3};\n"
                 : "+f"(c[0]), "+f"(c[1]), "+f"(c[2]), "+f"(c[3])
                 : "r"(a[0]), "r"(a[1]), "r"(a[2]), "r"(a[3]), "r"(b0), "r"(b1));
}
__device__ __forceinline__ void splitp(float x, float y, unsigned& h, unsigned& l) {
    __nv_bfloat162 hh = __floats2bfloat162_rn(x, y);
    float2 f = __bfloat1622float2(hh);
    __nv_bfloat162 ll = __floats2bfloat162_rn(x - f.x, y - f.y);
    h = *(unsigned*)&hh; l = *(unsigned*)&ll;
}
__device__ __forceinline__ void split4s(float4 v, __nv_bfloat16* dh, __nv_bfloat16* dl) {
    unsigned h0, l0, h1, l1;
    splitp(v.x, v.y, h0, l0); splitp(v.z, v.w, h1, l1);
    *(uint2*)dh = make_uint2(h0, h1);
    *(uint2*)dl = make_uint2(l0, l1);
}

// ---------------------------------------------------------------------------
// Pre-split weights (once). 64 CTAs x 256 thr, 3 float4/thread.
// ---------------------------------------------------------------------------
__global__ void splitw_kernel(const float* __restrict__ Wq,
                              const float* __restrict__ Wk,
                              const float* __restrict__ Wv)
{
    const float* Wsrc[3] = {Wq, Wk, Wv};
    int off = (blockIdx.x * 256 + threadIdx.x) * 4;
    #pragma unroll
    for (int mat = 0; mat < 3; ++mat) {
        float4 v = *(const float4*)&Wsrc[mat][off];
        split4s(v, &gWh3[mat*NEMB*HS + off], &gWl3[mat*NEMB*HS + off]);
    }
}

// ---------------------------------------------------------------------------
// Projection: one CTA = 64 rows of X -> Q,K,V (bf16x3 MMA), hi/lo outputs.
// ---------------------------------------------------------------------------
__global__ __launch_bounds__(256, 2) void proj_kernel(const float* __restrict__ x)
{
    extern __shared__ char smc[];
    __nv_bfloat16* sXh = (__nv_bfloat16*)smc;
    __nv_bfloat16* sXl = sXh + 64*LDB;
    __nv_bfloat16* sWh = sXl + 64*LDB;
    __nv_bfloat16* sWl = sWh + 3*64*LDB;

    const int bt0 = blockIdx.x * 64;
    const int tid = threadIdx.x, lane = tid & 31, wid = tid >> 5;
    const int wm = wid & 3, wn = wid >> 2;

    float acc[3][4][4];
    #pragma unroll
    for (int m = 0; m < 3; ++m)
        #pragma unroll
        for (int t = 0; t < 4; ++t)
            #pragma unroll
            for (int r = 0; r < 4; ++r) acc[m][t][r] = 0.f;

    for (int kt = 0; kt < NEMB/64; ++kt) {
        __syncthreads();
        #pragma unroll
        for (int r = 0; r < 4; ++r) {
            int u = tid + 256*r, row = u >> 4, c = (u & 15) * 4;
            float4 v = *(const float4*)&x[(size_t)(bt0+row)*NEMB + kt*64 + c];
            split4s(v, &sXh[row*LDB+c], &sXl[row*LDB+c]);
        }
        #pragma unroll
        for (int r = 0; r < 6; ++r) {
            int u = tid + 256*r;
            int mat = u >> 9, rem = u & 511;
            int row = rem >> 3, c = (rem & 7) * 8;
            size_t g = (size_t)mat*NEMB*HS + (size_t)(kt*64+row)*HS + c;
            int s = mat*64*LDB + row*LDB + c;
            *(uint4*)&sWh[s] = *(const uint4*)&gWh3[g];
            *(uint4*)&sWl[s] = *(const uint4*)&gWl3[g];
        }
        __syncthreads();

        #pragma unroll
        for (int kk = 0; kk < 4; ++kk) {
            unsigned ah[4], al[4];
            unsigned ao = (unsigned)(((wm*16 + (lane&15))*LDB + kk*16 + (lane>>4)*8) * 2);
            ldsm4(su32(sXh) + ao, ah);
            ldsm4(su32(sXl) + ao, al);
            #pragma unroll
            for (int mat = 0; mat < 3; ++mat) {
                #pragma unroll
                for (int nb = 0; nb < 2; ++nb) {
                    unsigned bh[4], bl[4];
                    unsigned bo = (unsigned)((mat*64*LDB + (kk*16 + (lane&15))*LDB +
                                              wn*32 + nb*16 + (lane>>4)*8) * 2);
                    ldsm4t(su32(sWh) + bo, bh);
                    ldsm4t(su32(sWl) + bo, bl);
                    float* c0 = acc[mat][nb*2]; float* c1 = acc[mat][nb*2+1];
                    mma16816(c0, ah, bh[0], bh[1]);
                    mma16816(c0, ah, bl[0], bl[1]);
                    mma16816(c0, al, bh[0], bh[1]);
                    mma16816(c1, ah, bh[2], bh[3]);
                    mma16816(c1, ah, bl[2], bl[3]);
                    mma16816(c1, al, bh[2], bh[3]);
                }
            }
        }
    }

    __nv_bfloat16* const GH[3] = {gQh, gKh, gVh};
    __nv_bfloat16* const GL[3] = {gQl, gKl, gVl};
    const int r0 = bt0 + wm*16 + (lane >> 2);
    #pragma unroll
    for (int mat = 0; mat < 3; ++mat)
        #pragma unroll
        for (int nt = 0; nt < 4; ++nt) {
            int col = wn*32 + nt*8 + 2*(lane & 3);
            unsigned h, l;
            splitp(acc[mat][nt][0], acc[mat][nt][1], h, l);
            *(unsigned*)&GH[mat][(size_t)r0*HS + col] = h;
            *(unsigned*)&GL[mat][(size_t)r0*HS + col] = l;
            splitp(acc[mat][nt][2], acc[mat][nt][3], h, l);
            *(unsigned*)&GH[mat][(size_t)(r0+8)*HS + col] = h;
            *(unsigned*)&GL[mat][(size_t)(r0+8)*HS + col] = l;
        }
}

// ---------------------------------------------------------------------------
// Flash attention, split-K. CTA = (chunk c, query tile qt, batch b).
// Chunk covers key tiles [c*CHK, min(qt, c*CHK+CHK-1)].
// qt<CHK: single chunk, writes out directly. Else writes partials (O,m,l).
// ---------------------------------------------------------------------------
__global__ __launch_bounds__(128, 3) void attn_kernel(float* __restrict__ out)
{
    const int c  = blockIdx.x;
    const int qt = NQT - 1 - blockIdx.y;   // heavy tiles first
    const int b  = blockIdx.z;
    const int nch = (qt >> 3) + 1;
    if (c >= nch) return;
    const int kt0 = c * CHK;
    const int kt1 = min(qt, kt0 + CHK - 1);
    const int t0 = qt * 64;

    extern __shared__ char smc[];
    __nv_bfloat16* sQh = (__nv_bfloat16*)smc;
    __nv_bfloat16* sQl = sQh + 64*LDB;
    __nv_bfloat16* sKh = sQl + 64*LDB;
    __nv_bfloat16* sKl = sKh + 64*LDB;
    __nv_bfloat16* sVh = sKl + 64*LDB;
    __nv_bfloat16* sVl = sVh + 64*LDB;

    const int tid = threadIdx.x, lane = tid & 31, w = tid >> 5;
    const int lr = lane >> 2;
    const int lc2 = 2 * (lane & 3);

    #pragma unroll
    for (int r = 0; r < 4; ++r) {
        int u = tid + 128*r, row = u >> 3, cc = (u & 7) * 8;
        size_t g = (size_t)(b*TT + t0 + row) * HS + cc;
        *(uint4*)&sQh[row*LDB + cc] = *(const uint4*)&gQh[g];
        *(uint4*)&sQl[row*LDB + cc] = *(const uint4*)&gQl[g];
    }
    __syncthreads();
    unsigned qh[4][4], ql[4][4];
    #pragma unroll
    for (int kk = 0; kk < 4; ++kk) {
        unsigned ao = (unsigned)(((w*16 + (lane&15))*LDB + kk*16 + (lane>>4)*8) * 2);
        ldsm4(su32(sQh) + ao, qh[kk]);
        ldsm4(su32(sQl) + ao, ql[kk]);
    }

    float o[8][4];
    #pragma unroll
    for (int t = 0; t < 8; ++t)
        #pragma unroll
        for (int r = 0; r < 4; ++r) o[t][r] = 0.f;
    float m0 = -1e30f, m1 = -1e30f, l0 = 0.f, l1 = 0.f;

    for (int kt = kt0; kt <= kt1; ++kt) {
        __syncthreads();
        #pragma unroll
        for (int r = 0; r < 4; ++r) {
            int u = tid + 128*r, row = u >> 3, cc = (u & 7) * 8;
            size_t g = (size_t)(b*TT + kt*64 + row) * HS + cc;
            int s = row*LDB + cc;
            *(uint4*)&sKh[s] = *(const uint4*)&gKh[g];
            *(uint4*)&sKl[s] = *(const uint4*)&gKl[g];
            *(uint4*)&sVh[s] = *(const uint4*)&gVh[g];
            *(uint4*)&sVl[s] = *(const uint4*)&gVl[g];
        }
        __syncthreads();

        float st[8][4];
        #pragma unroll
        for (int t = 0; t < 8; ++t)
            #pragma unroll
            for (int r = 0; r < 4; ++r) st[t][r] = 0.f;
        #pragma unroll
        for (int kk = 0; kk < 4; ++kk) {
            #pragma unroll
            for (int kb = 0; kb < 4; ++kb) {
                unsigned kh[4], kl[4];
                unsigned ko = (unsigned)(((kb*16 + (lane&15))*LDB + kk*16 + (lane>>4)*8) * 2);
                ldsm4(su32(sKh) + ko, kh);
                ldsm4(su32(sKl) + ko, kl);
                float* c0 = st[kb*2]; float* c1 = st[kb*2+1];
                mma16816(c0, qh[kk], kh[0], kh[2]);
                mma16816(c0, qh[kk], kl[0], kl[2]);
                mma16816(c0, ql[kk], kh[0], kh[2]);
                mma16816(c1, qh[kk], kh[1], kh[3]);
                mma16816(c1, qh[kk], kl[1], kl[3]);
                mma16816(c1, ql[kk], kh[1], kh[3]);
            }
        }

        if (kt == qt) {
            int r0 = w*16 + lr, r1 = r0 + 8;
            #pragma unroll
            for (int nt = 0; nt < 8; ++nt) {
                int cc = nt*8 + lc2;
                if (cc     > r0) st[nt][0] = -1e30f;
                if (cc + 1 > r0) st[nt][1] = -1e30f;
                if (cc     > r1) st[nt][2] = -1e30f;
                if (cc + 1 > r1) st[nt][3] = -1e30f;
            }
        }

        float mx0 = -1e30f, mx1 = -1e30f;
        #pragma unroll
        for (int nt = 0; nt < 8; ++nt) {
            mx0 = fmaxf(mx0, fmaxf(st[nt][0], st[nt][1]));
            mx1 = fmaxf(mx1, fmaxf(st[nt][2], st[nt][3]));
        }
        mx0 = fmaxf(mx0, __shfl_xor_sync(0xffffffffu, mx0, 1));
        mx0 = fmaxf(mx0, __shfl_xor_sync(0xffffffffu, mx0, 2));
        mx1 = fmaxf(mx1, __shfl_xor_sync(0xffffffffu, mx1, 1));
        mx1 = fmaxf(mx1, __shfl_xor_sync(0xffffffffu, mx1, 2));
        float mn0 = fmaxf(m0, mx0), mn1 = fmaxf(m1, mx1);
        float a0 = __expf(m0 - mn0), a1 = __expf(m1 - mn1);
        float s0 = 0.f, s1 = 0.f;
        #pragma unroll
        for (int nt = 0; nt < 8; ++nt) {
            st[nt][0] = __expf(st[nt][0] - mn0);
            st[nt][1] = __expf(st[nt][1] - mn0);
            st[nt][2] = __expf(st[nt][2] - mn1);
            st[nt][3] = __expf(st[nt][3] - mn1);
            s0 += st[nt][0] + st[nt][1];
            s1 += st[nt][2] + st[nt][3];
        }
        s0 += __shfl_xor_sync(0xffffffffu, s0, 1);
        s0 += __shfl_xor_sync(0xffffffffu, s0, 2);
        s1 += __shfl_xor_sync(0xffffffffu, s1, 1);
        s1 += __shfl_xor_sync(0xffffffffu, s1, 2);
        l0 = l0 * a0 + s0; l1 = l1 * a1 + s1;
        m0 = mn0; m1 = mn1;
        #pragma unroll
        for (int nt = 0; nt < 8; ++nt) {
            o[nt][0] *= a0; o[nt][1] *= a0; o[nt][2] *= a1; o[nt][3] *= a1;
        }

        unsigned ph[4][4], pl[4][4];
        #pragma unroll
        for (int t = 0; t < 4; ++t) {
            splitp(st[2*t][0],   st[2*t][1],   ph[t][0], pl[t][0]);
            splitp(st[2*t][2],   st[2*t][3],   ph[t][1], pl[t][1]);
            splitp(st[2*t+1][0], st[2*t+1][1], ph[t][2], pl[t][2]);
            splitp(st[2*t+1][2], st[2*t+1][3], ph[t][3], pl[t][3]);
        }
        #pragma unroll
        for (int t = 0; t < 4; ++t) {
            #pragma unroll
            for (int nb = 0; nb < 4; ++nb) {
                unsigned vh[4], vl[4];
                unsigned vo = (unsigned)(((t*16 + (lane&15))*LDB + nb*16 + (lane>>4)*8) * 2);
                ldsm4t(su32(sVh) + vo, vh);
                ldsm4t(su32(sVl) + vo, vl);
                float* c0 = o[nb*2]; float* c1 = o[nb*2+1];
                mma16816(c0, ph[t], vh[0], vh[1]);
                mma16816(c0, ph[t], vl[0], vl[1]);
                mma16816(c0, pl[t], vh[0], vh[1]);
                mma16816(c1, ph[t], vh[2], vh[3]);
                mma16816(c1, ph[t], vl[2], vl[3]);
                mma16816(c1, pl[t], vh[2], vh[3]);
            }
        }
    }

    const int rloc = w*16 + lr;   // row within tile
    if (nch == 1) {
        // single chunk: write normalized output directly
        float i0 = 1.f / l0, i1 = 1.f / l1;
        size_t gr0 = (size_t)(b*TT + t0 + rloc);
        #pragma unroll
        for (int nt = 0; nt < 8; ++nt) {
            int col = nt*8 + lc2;
            *(float2*)&out[gr0*HS + col]     = make_float2(o[nt][0]*i0, o[nt][1]*i0);
            *(float2*)&out[(gr0+8)*HS + col] = make_float2(o[nt][2]*i1, o[nt][3]*i1);
        }
    } else {
        size_t slot = (size_t)(b*NQT + qt)*MAXC + c;
        float* Op = gOp + slot*(64*HS);
        #pragma unroll
        for (int nt = 0; nt < 8; ++nt) {
            int col = nt*8 + lc2;
            *(float2*)&Op[rloc*HS + col]     = make_float2(o[nt][0], o[nt][1]);
            *(float2*)&Op[(rloc+8)*HS + col] = make_float2(o[nt][2], o[nt][3]);
        }
        if ((lane & 3) == 0) {
            gM[slot*64 + rloc] = m0;     gL[slot*64 + rloc] = l0;
            gM[slot*64 + rloc + 8] = m1; gL[slot*64 + rloc + 8] = l1;
        }
    }
}

// ---------------------------------------------------------------------------
// Merge split-K partials for qt >= CHK.
// ---------------------------------------------------------------------------
__global__ __launch_bounds__(256) void merge_kernel(float* __restrict__ out)
{
    const int qt = CHK + blockIdx.x;
    const int b  = blockIdx.y;
    const int nch = (qt >> 3) + 1;
    const int tid = threadIdx.x;
    const int row = tid >> 2;
    const int cb  = (tid & 3) * 16;
    const size_t slot0 = (size_t)(b*NQT + qt)*MAXC;

    float mv[MAXC], sc[MAXC];
    float ms = -1e30f;
    for (int c = 0; c < nch; ++c) {
        mv[c] = gM[(slot0 + c)*64 + row];
        ms = fmaxf(ms, mv[c]);
    }
    float lsum = 0.f;
    for (int c = 0; c < nch; ++c) {
        sc[c] = __expf(mv[c] - ms);
        lsum += gL[(slot0 + c)*64 + row] * sc[c];
    }
    float inv = 1.f / lsum;

    #pragma unroll
    for (int j = 0; j < 16; j += 4) {
        float4 acc = make_float4(0.f, 0.f, 0.f, 0.f);
        for (int c = 0; c < nch; ++c) {
            float4 v = *(const float4*)&gOp[(slot0 + c)*(64*HS) + row*HS + cb + j];
            acc.x += v.x * sc[c]; acc.y += v.y * sc[c];
            acc.z += v.z * sc[c]; acc.w += v.w * sc[c];
        }
        acc.x *= inv; acc.y *= inv; acc.z *= inv; acc.w *= inv;
        *(float4*)&out[(size_t)(b*TT + qt*64 + row)*HS + cb + j] = acc;
    }
}

// ---------------------------------------------------------------------------
static const int PROJ_SMEM = 8 * 64 * LDB * 2;   // 73728
static const int ATTN_SMEM = 6 * 64 * LDB * 2;   // 55296

extern "C" void kernel_launch(void* const* d_in, const int* in_sizes, int n_in,
                              void* d_out, int out_size)
{
    const float* x  = (const float*)d_in[0];
    const float* Wq = (const float*)d_in[1];
    const float* Wk = (const float*)d_in[2];
    const float* Wv = (const float*)d_in[3];
    float* out = (float*)d_out;
    (void)in_sizes; (void)n_in; (void)out_size;

    cudaFuncSetAttribute(proj_kernel, cudaFuncAttributeMaxDynamicSharedMemorySize, PROJ_SMEM);
    cudaFuncSetAttribute(attn_kernel, cudaFuncAttributeMaxDynamicSharedMemorySize, ATTN_SMEM);

    splitw_kernel<<<NEMB*HS/1024, 256>>>(Wq, Wk, Wv);
    proj_kernel<<<BT/64, 256, PROJ_SMEM>>>(x);
    attn_kernel<<<dim3(MAXC, NQT, BB), 128, ATTN_SMEM>>>(out);
    merge_kernel<<<dim3(NQT - CHK, BB), 256>>>(out);
}

// round 6
// speedup vs baseline: 1.3184x; 1.0485x over previous
#include <cuda_runtime.h>
#include <cuda_bf16.h>

#define NEMB 1024
#define HS 64
#define BB 8
#define TT 2048
#define BT (BB*TT)
#define LDB 72          // bf16 row stride for 64-wide tiles (144B, ldsm conflict-free)
#define LDX 40          // bf16 row stride for 32-wide X tiles (80B, conflict-free)
#define NQT (TT/64)
#define CHK 8
#define MAXC 4

__device__ __align__(16) __nv_bfloat16 gQh[BT*HS];
__device__ __align__(16) __nv_bfloat16 gQl[BT*HS];
__device__ __align__(16) __nv_bfloat16 gKh[BT*HS];
__device__ __align__(16) __nv_bfloat16 gKl[BT*HS];
__device__ __align__(16) __nv_bfloat16 gVh[BT*HS];
__device__ __align__(16) __nv_bfloat16 gVl[BT*HS];
__device__ __align__(16) __nv_bfloat16 gWh3[3*NEMB*HS];
__device__ __align__(16) __nv_bfloat16 gWl3[3*NEMB*HS];
__device__ __align__(16) float gOp[BB*NQT*MAXC*64*HS];
__device__ float gM[BB*NQT*MAXC*64];
__device__ float gL[BB*NQT*MAXC*64];

__device__ __forceinline__ unsigned su32(const void* p) {
    return (unsigned)__cvta_generic_to_shared(p);
}
__device__ __forceinline__ void cpa16(unsigned dst, const void* src) {
    asm volatile("cp.async.cg.shared.global [%0], [%1], 16;\n" :: "r"(dst), "l"(src));
}
__device__ __forceinline__ void cpcommit() {
    asm volatile("cp.async.commit_group;\n");
}
template<int N> __device__ __forceinline__ void cpwait() {
    asm volatile("cp.async.wait_group %0;\n" :: "n"(N));
}
__device__ __forceinline__ void ldsm4(unsigned a, unsigned* r) {
    asm volatile("ldmatrix.sync.aligned.m8n8.x4.shared.b16 {%0,%1,%2,%3},[%4];\n"
                 : "=r"(r[0]), "=r"(r[1]), "=r"(r[2]), "=r"(r[3]) : "r"(a));
}
__device__ __forceinline__ void ldsm4t(unsigned a, unsigned* r) {
    asm volatile("ldmatrix.sync.aligned.m8n8.x4.trans.shared.b16 {%0,%1,%2,%3},[%4];\n"
                 : "=r"(r[0]), "=r"(r[1]), "=r"(r[2]), "=r"(r[3]) : "r"(a));
}
__device__ __forceinline__ void mma16816(float* c, const unsigned* a, unsigned b0, unsigned b1) {
    asm volatile("mma.sync.aligned.m16n8k16.row.col.f32.bf16.bf16.f32 "
                 "{%0,%1,%2,%3},{%4,%5,%6,%7},{%8,%9},{%0,%1,%2,%3};\n"
                 : "+f"(c[0]), "+f"(c[1]), "+f"(c[2]), "+f"(c[3])
                 : "r"(a[0]), "r"(a[1]), "r"(a[2]), "r"(a[3]), "r"(b0), "r"(b1));
}
__device__ __forceinline__ void splitp(float x, float y, unsigned& h, unsigned& l) {
    __nv_bfloat162 hh = __floats2bfloat162_rn(x, y);
    float2 f = __bfloat1622float2(hh);
    __nv_bfloat162 ll = __floats2bfloat162_rn(x - f.x, y - f.y);
    h = *(unsigned*)&hh; l = *(unsigned*)&ll;
}
__device__ __forceinline__ void split4s(float4 v, __nv_bfloat16* dh, __nv_bfloat16* dl) {
    unsigned h0, l0, h1, l1;
    splitp(v.x, v.y, h0, l0); splitp(v.z, v.w, h1, l1);
    *(uint2*)dh = make_uint2(h0, h1);
    *(uint2*)dl = make_uint2(l0, l1);
}

// ---------------------------------------------------------------------------
__global__ void splitw_kernel(const float* __restrict__ Wq,
                              const float* __restrict__ Wk,
                              const float* __restrict__ Wv)
{
    const float* Wsrc[3] = {Wq, Wk, Wv};
    int off = (blockIdx.x * 256 + threadIdx.x) * 4;
    #pragma unroll
    for (int mat = 0; mat < 3; ++mat) {
        float4 v = *(const float4*)&Wsrc[mat][off];
        split4s(v, &gWh3[mat*NEMB*HS + off], &gWl3[mat*NEMB*HS + off]);
    }
}

// ---------------------------------------------------------------------------
// Projection: 64 rows of X -> Q,K,V. KT=32, double-buffered X (reg prefetch)
// and W (cp.async). One __syncthreads per iteration.
// smem: X 2 stages x (hi,lo) 64x40 bf16 (5120B each) = 20480
//       W 2 stages x 6 mat-halves x 32x72 bf16 (4608B each) = 55296
// ---------------------------------------------------------------------------
#define PROJ_XS(st, half) ((st)*10240 + (half)*5120)
#define PROJ_WS(st) (20480 + (st)*27648)
static const int PROJ_SMEM = 20480 + 2*27648;   // 75776

__global__ __launch_bounds__(256, 2) void proj_kernel(const float* __restrict__ x)
{
    extern __shared__ char smc[];
    const unsigned sb = su32(smc);

    const int bt0 = blockIdx.x * 64;
    const int tid = threadIdx.x, lane = tid & 31, wid = tid >> 5;
    const int wm = wid & 3, wn = wid >> 2;

    // loader geometry
    const int xrow0 = tid >> 3, xc0 = (tid & 7) * 4;           // X: u=tid
    const int xrow1 = (tid + 256) >> 3, xc1 = ((tid + 256) & 7) * 4;
    const unsigned wdst = (unsigned)((tid >> 3) * 144 + (tid & 7) * 16);

    float acc[3][4][4];
    #pragma unroll
    for (int m = 0; m < 3; ++m)
        #pragma unroll
        for (int t = 0; t < 4; ++t)
            #pragma unroll
            for (int r = 0; r < 4; ++r) acc[m][t][r] = 0.f;

    // issue W(0)
    {
        #pragma unroll
        for (int mh = 0; mh < 6; ++mh) {
            const __nv_bfloat16* src = (mh & 1) ? gWl3 : gWh3;
            const char* g = (const char*)(src + (mh>>1)*NEMB*HS) + (size_t)tid*16;
            cpa16(sb + PROJ_WS(0) + mh*4608 + wdst, g);
        }
        cpcommit();
    }
    // X(0) regs -> smem stage 0 ; prefetch X(1)
    float4 xr0, xr1;
    xr0 = *(const float4*)&x[(size_t)(bt0+xrow0)*NEMB + xc0];
    xr1 = *(const float4*)&x[(size_t)(bt0+xrow1)*NEMB + xc1];
    split4s(xr0, (__nv_bfloat16*)(smc + PROJ_XS(0,0)) + xrow0*LDX + xc0,
                 (__nv_bfloat16*)(smc + PROJ_XS(0,1)) + xrow0*LDX + xc0);
    split4s(xr1, (__nv_bfloat16*)(smc + PROJ_XS(0,0)) + xrow1*LDX + xc1,
                 (__nv_bfloat16*)(smc + PROJ_XS(0,1)) + xrow1*LDX + xc1);
    xr0 = *(const float4*)&x[(size_t)(bt0+xrow0)*NEMB + 32 + xc0];
    xr1 = *(const float4*)&x[(size_t)(bt0+xrow1)*NEMB + 32 + xc1];

    int buf = 0;
    for (int kt = 0; kt < 32; ++kt) {
        cpwait<0>();
        __syncthreads();
        if (kt < 31) {
            // issue W(kt+1) into other stage
            #pragma unroll
            for (int mh = 0; mh < 6; ++mh) {
                const __nv_bfloat16* src = (mh & 1) ? gWl3 : gWh3;
                const char* g = (const char*)(src + (mh>>1)*NEMB*HS)
                              + (size_t)(kt+1)*4096 + (size_t)tid*16;
                cpa16(sb + PROJ_WS(buf^1) + mh*4608 + wdst, g);
            }
            cpcommit();
            // store X(kt+1) into other stage
            split4s(xr0, (__nv_bfloat16*)(smc + PROJ_XS(buf^1,0)) + xrow0*LDX + xc0,
                         (__nv_bfloat16*)(smc + PROJ_XS(buf^1,1)) + xrow0*LDX + xc0);
            split4s(xr1, (__nv_bfloat16*)(smc + PROJ_XS(buf^1,0)) + xrow1*LDX + xc1,
                         (__nv_bfloat16*)(smc + PROJ_XS(buf^1,1)) + xrow1*LDX + xc1);
            if (kt < 30) {
                xr0 = *(const float4*)&x[(size_t)(bt0+xrow0)*NEMB + (kt+2)*32 + xc0];
                xr1 = *(const float4*)&x[(size_t)(bt0+xrow1)*NEMB + (kt+2)*32 + xc1];
            }
        }

        // compute on stage buf
        #pragma unroll
        for (int kk = 0; kk < 2; ++kk) {
            unsigned ah[4], al[4];
            unsigned ao = (unsigned)(((wm*16 + (lane&15))*LDX + kk*16 + (lane>>4)*8) * 2);
            ldsm4(sb + PROJ_XS(buf,0) + ao, ah);
            ldsm4(sb + PROJ_XS(buf,1) + ao, al);
            #pragma unroll
            for (int mat = 0; mat < 3; ++mat) {
                #pragma unroll
                for (int nb = 0; nb < 2; ++nb) {
                    unsigned bh[4], bl[4];
                    unsigned bo = (unsigned)(((kk*16 + (lane&15))*LDB +
                                              wn*32 + nb*16 + (lane>>4)*8) * 2);
                    ldsm4t(sb + PROJ_WS(buf) + (mat*2  )*4608 + bo, bh);
                    ldsm4t(sb + PROJ_WS(buf) + (mat*2+1)*4608 + bo, bl);
                    float* c0 = acc[mat][nb*2]; float* c1 = acc[mat][nb*2+1];
                    mma16816(c0, ah, bh[0], bh[1]);
                    mma16816(c0, ah, bl[0], bl[1]);
                    mma16816(c0, al, bh[0], bh[1]);
                    mma16816(c1, ah, bh[2], bh[3]);
                    mma16816(c1, ah, bl[2], bl[3]);
                    mma16816(c1, al, bh[2], bh[3]);
                }
            }
        }
        buf ^= 1;
    }

    __nv_bfloat16* const GH[3] = {gQh, gKh, gVh};
    __nv_bfloat16* const GL[3] = {gQl, gKl, gVl};
    const int r0 = bt0 + wm*16 + (lane >> 2);
    #pragma unroll
    for (int mat = 0; mat < 3; ++mat)
        #pragma unroll
        for (int nt = 0; nt < 4; ++nt) {
            int col = wn*32 + nt*8 + 2*(lane & 3);
            unsigned h, l;
            splitp(acc[mat][nt][0], acc[mat][nt][1], h, l);
            *(unsigned*)&GH[mat][(size_t)r0*HS + col] = h;
            *(unsigned*)&GL[mat][(size_t)r0*HS + col] = l;
            splitp(acc[mat][nt][2], acc[mat][nt][3], h, l);
            *(unsigned*)&GH[mat][(size_t)(r0+8)*HS + col] = h;
            *(unsigned*)&GL[mat][(size_t)(r0+8)*HS + col] = l;
        }
}

// ---------------------------------------------------------------------------
// Flash attention, split-K, double-buffered K/V via cp.async (Q reuses stage 1).
// smem: 2 stages x 4 mats x 9216B = 73728.
// ---------------------------------------------------------------------------
#define AT_ST(s)  ((s)*36864)
#define AT_KH(s)  (AT_ST(s) + 0)
#define AT_KL(s)  (AT_ST(s) + 9216)
#define AT_VH(s)  (AT_ST(s) + 18432)
#define AT_VL(s)  (AT_ST(s) + 27648)
static const int ATTN_SMEM = 2*4*9216;   // 73728

__global__ __launch_bounds__(128, 3) void attn_kernel(float* __restrict__ out)
{
    const int c  = blockIdx.x;
    const int qt = NQT - 1 - blockIdx.y;
    const int b  = blockIdx.z;
    const int nch = (qt >> 3) + 1;
    if (c >= nch) return;
    const int kt0 = c * CHK;
    const int kt1 = min(qt, kt0 + CHK - 1);
    const int t0 = qt * 64;

    extern __shared__ char smc[];
    const unsigned sb = su32(smc);

    const int tid = threadIdx.x, lane = tid & 31, w = tid >> 5;
    const int lr = lane >> 2;
    const int lc2 = 2 * (lane & 3);

    // cp.async dst geometry: per-mat, u = tid + 128*r, dst = (u>>3)*144 + (u&7)*16
    unsigned d16[4];
    #pragma unroll
    for (int r = 0; r < 4; ++r) {
        int u = tid + 128*r;
        d16[r] = (unsigned)((u>>3)*144 + (u&7)*16);
    }

    // prologue: Q -> stage1 (Kh,Kl slots)
    {
        const char* gq = (const char*)gQh + (size_t)(b*TT + t0)*128;
        const char* gl = (const char*)gQl + (size_t)(b*TT + t0)*128;
        #pragma unroll
        for (int r = 0; r < 4; ++r) {
            int u = tid + 128*r;
            cpa16(sb + AT_KH(1) + d16[r], gq + (size_t)u*16);
            cpa16(sb + AT_KL(1) + d16[r], gl + (size_t)u*16);
        }
        cpcommit();
    }
    // K/V(kt0) -> stage0
    {
        size_t gb = (size_t)(b*TT + kt0*64)*128;
        #pragma unroll
        for (int r = 0; r < 4; ++r) {
            int u = tid + 128*r;
            size_t go = gb + (size_t)u*16;
            cpa16(sb + AT_KH(0) + d16[r], (const char*)gKh + go);
            cpa16(sb + AT_KL(0) + d16[r], (const char*)gKl + go);
            cpa16(sb + AT_VH(0) + d16[r], (const char*)gVh + go);
            cpa16(sb + AT_VL(0) + d16[r], (const char*)gVl + go);
        }
        cpcommit();
    }

    cpwait<1>();          // Q arrived (KV may be in flight)
    __syncthreads();
    unsigned qh[4][4], ql[4][4];
    #pragma unroll
    for (int kk = 0; kk < 4; ++kk) {
        unsigned ao = (unsigned)(((w*16 + (lane&15))*LDB + kk*16 + (lane>>4)*8) * 2);
        ldsm4(sb + AT_KH(1) + ao, qh[kk]);
        ldsm4(sb + AT_KL(1) + ao, ql[kk]);
    }

    float o[8][4];
    #pragma unroll
    for (int t = 0; t < 8; ++t)
        #pragma unroll
        for (int r = 0; r < 4; ++r) o[t][r] = 0.f;
    float m0 = -1e30f, m1 = -1e30f, l0 = 0.f, l1 = 0.f;

    int buf = 0;
    for (int kt = kt0; kt <= kt1; ++kt) {
        cpwait<0>();
        __syncthreads();   // data visible; all warps done with prev stage + Q reads
        if (kt < kt1) {
            size_t gb = (size_t)(b*TT + (kt+1)*64)*128;
            #pragma unroll
            for (int r = 0; r < 4; ++r) {
                int u = tid + 128*r;
                size_t go = gb + (size_t)u*16;
                cpa16(sb + AT_KH(buf^1) + d16[r], (const char*)gKh + go);
                cpa16(sb + AT_KL(buf^1) + d16[r], (const char*)gKl + go);
                cpa16(sb + AT_VH(buf^1) + d16[r], (const char*)gVh + go);
                cpa16(sb + AT_VL(buf^1) + d16[r], (const char*)gVl + go);
            }
            cpcommit();
        }

        // S = Q K^T (bf16x3)
        float st[8][4];
        #pragma unroll
        for (int t = 0; t < 8; ++t)
            #pragma unroll
            for (int r = 0; r < 4; ++r) st[t][r] = 0.f;
        #pragma unroll
        for (int kk = 0; kk < 4; ++kk) {
            #pragma unroll
            for (int kb = 0; kb < 4; ++kb) {
                unsigned kh[4], kl[4];
                unsigned ko = (unsigned)(((kb*16 + (lane&15))*LDB + kk*16 + (lane>>4)*8) * 2);
                ldsm4(sb + AT_KH(buf) + ko, kh);
                ldsm4(sb + AT_KL(buf) + ko, kl);
                float* c0 = st[kb*2]; float* c1 = st[kb*2+1];
                mma16816(c0, qh[kk], kh[0], kh[2]);
                mma16816(c0, qh[kk], kl[0], kl[2]);
                mma16816(c0, ql[kk], kh[0], kh[2]);
                mma16816(c1, qh[kk], kh[1], kh[3]);
                mma16816(c1, qh[kk], kl[1], kl[3]);
                mma16816(c1, ql[kk], kh[1], kh[3]);
            }
        }

        if (kt == qt) {
            int r0 = w*16 + lr, r1 = r0 + 8;
            #pragma unroll
            for (int nt = 0; nt < 8; ++nt) {
                int cc = nt*8 + lc2;
                if (cc     > r0) st[nt][0] = -1e30f;
                if (cc + 1 > r0) st[nt][1] = -1e30f;
                if (cc     > r1) st[nt][2] = -1e30f;
                if (cc + 1 > r1) st[nt][3] = -1e30f;
            }
        }

        float mx0 = -1e30f, mx1 = -1e30f;
        #pragma unroll
        for (int nt = 0; nt < 8; ++nt) {
            mx0 = fmaxf(mx0, fmaxf(st[nt][0], st[nt][1]));
            mx1 = fmaxf(mx1, fmaxf(st[nt][2], st[nt][3]));
        }
        mx0 = fmaxf(mx0, __shfl_xor_sync(0xffffffffu, mx0, 1));
        mx0 = fmaxf(mx0, __shfl_xor_sync(0xffffffffu, mx0, 2));
        mx1 = fmaxf(mx1, __shfl_xor_sync(0xffffffffu, mx1, 1));
        mx1 = fmaxf(mx1, __shfl_xor_sync(0xffffffffu, mx1, 2));
        float mn0 = fmaxf(m0, mx0), mn1 = fmaxf(m1, mx1);
        float a0 = __expf(m0 - mn0), a1 = __expf(m1 - mn1);
        float s0 = 0.f, s1 = 0.f;
        #pragma unroll
        for (int nt = 0; nt < 8; ++nt) {
            st[nt][0] = __expf(st[nt][0] - mn0);
            st[nt][1] = __expf(st[nt][1] - mn0);
            st[nt][2] = __expf(st[nt][2] - mn1);
            st[nt][3] = __expf(st[nt][3] - mn1);
            s0 += st[nt][0] + st[nt][1];
            s1 += st[nt][2] + st[nt][3];
        }
        s0 += __shfl_xor_sync(0xffffffffu, s0, 1);
        s0 += __shfl_xor_sync(0xffffffffu, s0, 2);
        s1 += __shfl_xor_sync(0xffffffffu, s1, 1);
        s1 += __shfl_xor_sync(0xffffffffu, s1, 2);
        l0 = l0 * a0 + s0; l1 = l1 * a1 + s1;
        m0 = mn0; m1 = mn1;
        #pragma unroll
        for (int nt = 0; nt < 8; ++nt) {
            o[nt][0] *= a0; o[nt][1] *= a0; o[nt][2] *= a1; o[nt][3] *= a1;
        }

        unsigned ph[4][4], pl[4][4];
        #pragma unroll
        for (int t = 0; t < 4; ++t) {
            splitp(st[2*t][0],   st[2*t][1],   ph[t][0], pl[t][0]);
            splitp(st[2*t][2],   st[2*t][3],   ph[t][1], pl[t][1]);
            splitp(st[2*t+1][0], st[2*t+1][1], ph[t][2], pl[t][2]);
            splitp(st[2*t+1][2], st[2*t+1][3], ph[t][3], pl[t][3]);
        }
        #pragma unroll
        for (int t = 0; t < 4; ++t) {
            #pragma unroll
            for (int nb = 0; nb < 4; ++nb) {
                unsigned vh[4], vl[4];
                unsigned vo = (unsigned)(((t*16 + (lane&15))*LDB + nb*16 + (lane>>4)*8) * 2);
                ldsm4t(sb + AT_VH(buf) + vo, vh);
                ldsm4t(sb + AT_VL(buf) + vo, vl);
                float* c0 = o[nb*2]; float* c1 = o[nb*2+1];
                mma16816(c0, ph[t], vh[0], vh[1]);
                mma16816(c0, ph[t], vl[0], vl[1]);
                mma16816(c0, pl[t], vh[0], vh[1]);
                mma16816(c1, ph[t], vh[2], vh[3]);
                mma16816(c1, ph[t], vl[2], vl[3]);
                mma16816(c1, pl[t], vh[2], vh[3]);
            }
        }
        buf ^= 1;
    }

    const int rloc = w*16 + lr;
    if (nch == 1) {
        float i0 = 1.f / l0, i1 = 1.f / l1;
        size_t gr0 = (size_t)(b*TT + t0 + rloc);
        #pragma unroll
        for (int nt = 0; nt < 8; ++nt) {
            int col = nt*8 + lc2;
            *(float2*)&out[gr0*HS + col]     = make_float2(o[nt][0]*i0, o[nt][1]*i0);
            *(float2*)&out[(gr0+8)*HS + col] = make_float2(o[nt][2]*i1, o[nt][3]*i1);
        }
    } else {
        size_t slot = (size_t)(b*NQT + qt)*MAXC + c;
        float* Op = gOp + slot*(64*HS);
        #pragma unroll
        for (int nt = 0; nt < 8; ++nt) {
            int col = nt*8 + lc2;
            *(float2*)&Op[rloc*HS + col]     = make_float2(o[nt][0], o[nt][1]);
            *(float2*)&Op[(rloc+8)*HS + col] = make_float2(o[nt][2], o[nt][3]);
        }
        if ((lane & 3) == 0) {
            gM[slot*64 + rloc] = m0;     gL[slot*64 + rloc] = l0;
            gM[slot*64 + rloc + 8] = m1; gL[slot*64 + rloc + 8] = l1;
        }
    }
}

// ---------------------------------------------------------------------------
// Merge split-K partials; grid (NQT-CHK, BB, 4): block z handles 16 cols.
// ---------------------------------------------------------------------------
__global__ __launch_bounds__(256) void merge_kernel(float* __restrict__ out)
{
    const int qt = CHK + blockIdx.x;
    const int b  = blockIdx.y;
    const int z  = blockIdx.z;
    const int nch = (qt >> 3) + 1;
    const int tid = threadIdx.x;
    const int row = tid >> 2;
    const int col = z*16 + (tid & 3) * 4;
    const size_t slot0 = (size_t)(b*NQT + qt)*MAXC;

    float ms = -1e30f;
    float mv[MAXC];
    #pragma unroll
    for (int c = 0; c < MAXC; ++c) {
        if (c < nch) { mv[c] = gM[(slot0 + c)*64 + row]; ms = fmaxf(ms, mv[c]); }
    }
    float lsum = 0.f;
    float sc[MAXC];
    #pragma unroll
    for (int c = 0; c < MAXC; ++c) {
        if (c < nch) {
            sc[c] = __expf(mv[c] - ms);
            lsum += gL[(slot0 + c)*64 + row] * sc[c];
        }
    }
    float inv = 1.f / lsum;

    float4 acc = make_float4(0.f, 0.f, 0.f, 0.f);
    #pragma unroll
    for (int c = 0; c < MAXC; ++c) {
        if (c < nch) {
            float4 v = *(const float4*)&gOp[(slot0 + c)*(64*HS) + row*HS + col];
            acc.x += v.x * sc[c]; acc.y += v.y * sc[c];
            acc.z += v.z * sc[c]; acc.w += v.w * sc[c];
        }
    }
    acc.x *= inv; acc.y *= inv; acc.z *= inv; acc.w *= inv;
    *(float4*)&out[(size_t)(b*TT + qt*64 + row)*HS + col] = acc;
}

// ---------------------------------------------------------------------------
extern "C" void kernel_launch(void* const* d_in, const int* in_sizes, int n_in,
                              void* d_out, int out_size)
{
    const float* x  = (const float*)d_in[0];
    const float* Wq = (const float*)d_in[1];
    const float* Wk = (const float*)d_in[2];
    const float* Wv = (const float*)d_in[3];
    float* out = (float*)d_out;
    (void)in_sizes; (void)n_in; (void)out_size;

    cudaFuncSetAttribute(proj_kernel, cudaFuncAttributeMaxDynamicSharedMemorySize, PROJ_SMEM);
    cudaFuncSetAttribute(attn_kernel, cudaFuncAttributeMaxDynamicSharedMemorySize, ATTN_SMEM);

    splitw_kernel<<<NEMB*HS/1024, 256>>>(Wq, Wk, Wv);
    proj_kernel<<<BT/64, 256, PROJ_SMEM>>>(x);
    attn_kernel<<<dim3(MAXC, NQT, BB), 128, ATTN_SMEM>>>(out);
    merge_kernel<<<dim3(NQT - CHK, BB, 4), 256>>>(out);
}

// round 9
// speedup vs baseline: 1.3220x; 1.0028x over previous
#include <cuda_runtime.h>
#include <cuda_bf16.h>
#include <cstdint>

#define NEMB 1024
#define HS 64
#define BB 8
#define TT 2048
#define BT (BB*TT)
#define LDB 72          // bf16 row stride for 64-wide tiles (144B, ldsm conflict-free)
#define LDX 40          // bf16 row stride for 32-wide X tiles (80B, conflict-free)
#define NQT (TT/64)
#define CHK 8
#define MAXC 4

__device__ __align__(16) __nv_bfloat16 gQh[BT*HS];
__device__ __align__(16) __nv_bfloat16 gQl[BT*HS];
__device__ __align__(16) __nv_bfloat16 gKh[BT*HS];
__device__ __align__(16) __nv_bfloat16 gKl[BT*HS];
__device__ __align__(16) __nv_bfloat16 gVh[BT*HS];
__device__ __align__(16) __nv_bfloat16 gVl[BT*HS];
// pre-split weights, [mat][k][n] layout
__device__ __align__(16) __nv_bfloat16 gWh3[3*NEMB*HS];
__device__ __align__(16) __nv_bfloat16 gWl3[3*NEMB*HS];
__device__ __align__(16) float gOp[BB*NQT*MAXC*64*HS];
__device__ float gM[BB*NQT*MAXC*64];
__device__ float gL[BB*NQT*MAXC*64];

__device__ __forceinline__ unsigned su32(const void* p) {
    return (unsigned)__cvta_generic_to_shared(p);
}
__device__ __forceinline__ void cpa16(unsigned dst, const void* src) {
    asm volatile("cp.async.cg.shared.global [%0], [%1], 16;\n" :: "r"(dst), "l"(src));
}
__device__ __forceinline__ void cpcommit() { asm volatile("cp.async.commit_group;\n"); }
template<int N> __device__ __forceinline__ void cpwait() {
    asm volatile("cp.async.wait_group %0;\n" :: "n"(N));
}
__device__ __forceinline__ void ldsm4(unsigned a, unsigned* r) {
    asm volatile("ldmatrix.sync.aligned.m8n8.x4.shared.b16 {%0,%1,%2,%3},[%4];\n"
                 : "=r"(r[0]), "=r"(r[1]), "=r"(r[2]), "=r"(r[3]) : "r"(a));
}
__device__ __forceinline__ void ldsm4t(unsigned a, unsigned* r) {
    asm volatile("ldmatrix.sync.aligned.m8n8.x4.trans.shared.b16 {%0,%1,%2,%3},[%4];\n"
                 : "=r"(r[0]), "=r"(r[1]), "=r"(r[2]), "=r"(r[3]) : "r"(a));
}
__device__ __forceinline__ void mma16816(float* c, const unsigned* a, unsigned b0, unsigned b1) {
    asm volatile("mma.sync.aligned.m16n8k16.row.col.f32.bf16.bf16.f32 "
                 "{%0,%1,%2,%3},{%4,%5,%6,%7},{%8,%9},{%0,%1,%2,%3};\n"
                 : "+f"(c[0]), "+f"(c[1]), "+f"(c[2]), "+f"(c[3])
                 : "r"(a[0]), "r"(a[1]), "r"(a[2]), "r"(a[3]), "r"(b0), "r"(b1));
}
__device__ __forceinline__ void splitp(float x, float y, unsigned& h, unsigned& l) {
    __nv_bfloat162 hh = __floats2bfloat162_rn(x, y);
    float2 f = __bfloat1622float2(hh);
    __nv_bfloat162 ll = __floats2bfloat162_rn(x - f.x, y - f.y);
    h = *(unsigned*)&hh; l = *(unsigned*)&ll;
}
__device__ __forceinline__ void split4s(float4 v, __nv_bfloat16* dh, __nv_bfloat16* dl) {
    unsigned h0, l0, h1, l1;
    splitp(v.x, v.y, h0, l0); splitp(v.z, v.w, h1, l1);
    *(uint2*)dh = make_uint2(h0, h1);
    *(uint2*)dl = make_uint2(l0, l1);
}

// ---------------------------------------------------------------------------
// Pre-split weights (once). 64 CTAs x 256 thr, 3 float4/thread.
// ---------------------------------------------------------------------------
__global__ void splitw_kernel(const float* __restrict__ Wq,
                              const float* __restrict__ Wk,
                              const float* __restrict__ Wv)
{
    const float* Wsrc[3] = {Wq, Wk, Wv};
    int off = (blockIdx.x * 256 + threadIdx.x) * 4;
    #pragma unroll
    for (int mat = 0; mat < 3; ++mat) {
        float4 v = *(const float4*)&Wsrc[mat][off];
        split4s(v, &gWh3[mat*NEMB*HS + off], &gWl3[mat*NEMB*HS + off]);
    }
}

// ---------------------------------------------------------------------------
// Projection: 128 rows of X per CTA -> Q,K,V (bf16x3 MMA), hi/lo outputs.
// 512 threads = 16 warps: 8 m-groups x 2 n-groups. KT=32, double-buffered
// X (register prefetch) and W (cp.async). One __syncthreads per iteration.
// smem/stage: X hi/lo 128x40 bf16 (10240B each) + W 6 slabs x 32x72 (4608B).
// ---------------------------------------------------------------------------
#define PJ_BLK 48128
#define PJ_X(s,h)    ((s)*PJ_BLK + (h)*10240)
#define PJ_W(s,slab) ((s)*PJ_BLK + 20480 + (slab)*4608)
static const int PROJ_SMEM = 2*PJ_BLK;   // 96256

__global__ __launch_bounds__(512) void proj_kernel(const float* __restrict__ x)
{
    extern __shared__ char smc[];
    const unsigned sb = su32(smc);
    const int tid = threadIdx.x, lane = tid & 31, wid = tid >> 5;
    const int wm = wid & 7, wn = wid >> 3;
    const int bt0 = blockIdx.x * 128;

    // X loader geometry: 2 float4 per thread (128 rows x 8 f4/row = 1024)
    const int xrow0 = tid >> 3, xc0 = (tid & 7) * 4;
    const int xrow1 = (tid + 512) >> 3, xc1 = ((tid + 512) & 7) * 4;

    float acc[3][4][4];
    #pragma unroll
    for (int m = 0; m < 3; ++m)
        #pragma unroll
        for (int t = 0; t < 4; ++t)
            #pragma unroll
            for (int r = 0; r < 4; ++r) acc[m][t][r] = 0.f;

    // issue W(0): 3 cpa16 per thread (6 slabs x 256 chunks = 1536)
    #pragma unroll
    for (int r = 0; r < 3; ++r) {
        int u = tid + 512*r;
        int slab = u >> 8, rem = u & 255;
        int row = rem >> 3, c16 = rem & 7;
        const __nv_bfloat16* base = (slab & 1) ? gWl3 : gWh3;
        const char* src = (const char*)(base + (size_t)(slab>>1)*NEMB*HS)
                        + ((size_t)row*HS + c16*8) * 2;
        cpa16(sb + PJ_W(0, slab) + row*144 + c16*16, src);
    }
    cpcommit();
    // X(0) -> smem stage 0 ; prefetch X(1) into regs
    float4 xr0, xr1;
    xr0 = *(const float4*)&x[(size_t)(bt0+xrow0)*NEMB + xc0];
    xr1 = *(const float4*)&x[(size_t)(bt0+xrow1)*NEMB + xc1];
    split4s(xr0, (__nv_bfloat16*)(smc + PJ_X(0,0)) + xrow0*LDX + xc0,
                 (__nv_bfloat16*)(smc + PJ_X(0,1)) + xrow0*LDX + xc0);
    split4s(xr1, (__nv_bfloat16*)(smc + PJ_X(0,0)) + xrow1*LDX + xc1,
                 (__nv_bfloat16*)(smc + PJ_X(0,1)) + xrow1*LDX + xc1);
    xr0 = *(const float4*)&x[(size_t)(bt0+xrow0)*NEMB + 32 + xc0];
    xr1 = *(const float4*)&x[(size_t)(bt0+xrow1)*NEMB + 32 + xc1];

    int buf = 0;
    for (int kt = 0; kt < 32; ++kt) {
        cpwait<0>();
        __syncthreads();
        if (kt < 31) {
            // issue W(kt+1) into other stage
            #pragma unroll
            for (int r = 0; r < 3; ++r) {
                int u = tid + 512*r;
                int slab = u >> 8, rem = u & 255;
                int row = rem >> 3, c16 = rem & 7;
                const __nv_bfloat16* base = (slab & 1) ? gWl3 : gWh3;
                const char* src = (const char*)(base + (size_t)(slab>>1)*NEMB*HS)
                                + ((size_t)((kt+1)*32 + row)*HS + c16*8) * 2;
                cpa16(sb + PJ_W(buf^1, slab) + row*144 + c16*16, src);
            }
            cpcommit();
            // store X(kt+1) into other stage
            split4s(xr0, (__nv_bfloat16*)(smc + PJ_X(buf^1,0)) + xrow0*LDX + xc0,
                         (__nv_bfloat16*)(smc + PJ_X(buf^1,1)) + xrow0*LDX + xc0);
            split4s(xr1, (__nv_bfloat16*)(smc + PJ_X(buf^1,0)) + xrow1*LDX + xc1,
                         (__nv_bfloat16*)(smc + PJ_X(buf^1,1)) + xrow1*LDX + xc1);
            if (kt < 30) {
                xr0 = *(const float4*)&x[(size_t)(bt0+xrow0)*NEMB + (kt+2)*32 + xc0];
                xr1 = *(const float4*)&x[(size_t)(bt0+xrow1)*NEMB + (kt+2)*32 + xc1];
            }
        }

        // compute on stage buf
        #pragma unroll
        for (int kk = 0; kk < 2; ++kk) {
            unsigned ah[4], al[4];
            unsigned ao = (unsigned)(((wm*16 + (lane&15))*LDX + kk*16 + (lane>>4)*8) * 2);
            ldsm4(sb + PJ_X(buf,0) + ao, ah);
            ldsm4(sb + PJ_X(buf,1) + ao, al);
            #pragma unroll
            for (int mat = 0; mat < 3; ++mat) {
                #pragma unroll
                for (int nb = 0; nb < 2; ++nb) {
                    unsigned bh[4], bl[4];
                    unsigned bo = (unsigned)(((kk*16 + (lane&15))*LDB +
                                              wn*32 + nb*16 + (lane>>4)*8) * 2);
                    ldsm4t(sb + PJ_W(buf, mat*2)     + bo, bh);
                    ldsm4t(sb + PJ_W(buf, mat*2 + 1) + bo, bl);
                    float* c0 = acc[mat][nb*2]; float* c1 = acc[mat][nb*2+1];
                    mma16816(c0, ah, bh[0], bh[1]);
                    mma16816(c0, ah, bl[0], bl[1]);
                    mma16816(c0, al, bh[0], bh[1]);
                    mma16816(c1, ah, bh[2], bh[3]);
                    mma16816(c1, ah, bl[2], bl[3]);
                    mma16816(c1, al, bh[2], bh[3]);
                }
            }
        }
        buf ^= 1;
    }

    __nv_bfloat16* const GH[3] = {gQh, gKh, gVh};
    __nv_bfloat16* const GL[3] = {gQl, gKl, gVl};
    const int r0 = bt0 + wm*16 + (lane >> 2);
    #pragma unroll
    for (int mat = 0; mat < 3; ++mat)
        #pragma unroll
        for (int nt = 0; nt < 4; ++nt) {
            int col = wn*32 + nt*8 + 2*(lane & 3);
            unsigned h, l;
            splitp(acc[mat][nt][0], acc[mat][nt][1], h, l);
            *(unsigned*)&GH[mat][(size_t)r0*HS + col] = h;
            *(unsigned*)&GL[mat][(size_t)r0*HS + col] = l;
            splitp(acc[mat][nt][2], acc[mat][nt][3], h, l);
            *(unsigned*)&GH[mat][(size_t)(r0+8)*HS + col] = h;
            *(unsigned*)&GL[mat][(size_t)(r0+8)*HS + col] = l;
        }
}

// ---------------------------------------------------------------------------
// Flash attention, split-K, double-buffered K/V via cp.async (R6, unchanged).
// ---------------------------------------------------------------------------
#define AT_ST(s)  ((s)*36864)
#define AT_KH(s)  (AT_ST(s) + 0)
#define AT_KL(s)  (AT_ST(s) + 9216)
#define AT_VH(s)  (AT_ST(s) + 18432)
#define AT_VL(s)  (AT_ST(s) + 27648)
static const int ATTN_SMEM = 2*4*9216;   // 73728

__global__ __launch_bounds__(128, 3) void attn_kernel(float* __restrict__ out)
{
    const int c  = blockIdx.x;
    const int qt = NQT - 1 - blockIdx.y;
    const int b  = blockIdx.z;
    const int nch = (qt >> 3) + 1;
    if (c >= nch) return;
    const int kt0 = c * CHK;
    const int kt1 = min(qt, kt0 + CHK - 1);
    const int t0 = qt * 64;

    extern __shared__ char smc[];
    const unsigned sb = su32(smc);
    const int tid = threadIdx.x, lane = tid & 31, w = tid >> 5;
    const int lr = lane >> 2;
    const int lc2 = 2 * (lane & 3);

    unsigned d16[4];
    #pragma unroll
    for (int r = 0; r < 4; ++r) {
        int u = tid + 128*r;
        d16[r] = (unsigned)((u>>3)*144 + (u&7)*16);
    }

    {
        const char* gq = (const char*)gQh + (size_t)(b*TT + t0)*128;
        const char* gl = (const char*)gQl + (size_t)(b*TT + t0)*128;
        #pragma unroll
        for (int r = 0; r < 4; ++r) {
            int u = tid + 128*r;
            cpa16(sb + AT_KH(1) + d16[r], gq + (size_t)u*16);
            cpa16(sb + AT_KL(1) + d16[r], gl + (size_t)u*16);
        }
        cpcommit();
    }
    {
        size_t gb = (size_t)(b*TT + kt0*64)*128;
        #pragma unroll
        for (int r = 0; r < 4; ++r) {
            int u = tid + 128*r;
            size_t go = gb + (size_t)u*16;
            cpa16(sb + AT_KH(0) + d16[r], (const char*)gKh + go);
            cpa16(sb + AT_KL(0) + d16[r], (const char*)gKl + go);
            cpa16(sb + AT_VH(0) + d16[r], (const char*)gVh + go);
            cpa16(sb + AT_VL(0) + d16[r], (const char*)gVl + go);
        }
        cpcommit();
    }

    cpwait<1>();
    __syncthreads();
    unsigned qh[4][4], ql[4][4];
    #pragma unroll
    for (int kk = 0; kk < 4; ++kk) {
        unsigned ao = (unsigned)(((w*16 + (lane&15))*LDB + kk*16 + (lane>>4)*8) * 2);
        ldsm4(sb + AT_KH(1) + ao, qh[kk]);
        ldsm4(sb + AT_KL(1) + ao, ql[kk]);
    }

    float o[8][4];
    #pragma unroll
    for (int t = 0; t < 8; ++t)
        #pragma unroll
        for (int r = 0; r < 4; ++r) o[t][r] = 0.f;
    float m0 = -1e30f, m1 = -1e30f, l0 = 0.f, l1 = 0.f;

    int buf = 0;
    for (int kt = kt0; kt <= kt1; ++kt) {
        cpwait<0>();
        __syncthreads();
        if (kt < kt1) {
            size_t gb = (size_t)(b*TT + (kt+1)*64)*128;
            #pragma unroll
            for (int r = 0; r < 4; ++r) {
                int u = tid + 128*r;
                size_t go = gb + (size_t)u*16;
                cpa16(sb + AT_KH(buf^1) + d16[r], (const char*)gKh + go);
                cpa16(sb + AT_KL(buf^1) + d16[r], (const char*)gKl + go);
                cpa16(sb + AT_VH(buf^1) + d16[r], (const char*)gVh + go);
                cpa16(sb + AT_VL(buf^1) + d16[r], (const char*)gVl + go);
            }
            cpcommit();
        }

        float st[8][4];
        #pragma unroll
        for (int t = 0; t < 8; ++t)
            #pragma unroll
            for (int r = 0; r < 4; ++r) st[t][r] = 0.f;
        #pragma unroll
        for (int kk = 0; kk < 4; ++kk) {
            #pragma unroll
            for (int kb = 0; kb < 4; ++kb) {
                unsigned kh[4], kl[4];
                unsigned ko = (unsigned)(((kb*16 + (lane&15))*LDB + kk*16 + (lane>>4)*8) * 2);
                ldsm4(sb + AT_KH(buf) + ko, kh);
                ldsm4(sb + AT_KL(buf) + ko, kl);
                float* c0 = st[kb*2]; float* c1 = st[kb*2+1];
                mma16816(c0, qh[kk], kh[0], kh[2]);
                mma16816(c0, qh[kk], kl[0], kl[2]);
                mma16816(c0, ql[kk], kh[0], kh[2]);
                mma16816(c1, qh[kk], kh[1], kh[3]);
                mma16816(c1, qh[kk], kl[1], kl[3]);
                mma16816(c1, ql[kk], kh[1], kh[3]);
            }
        }

        if (kt == qt) {
            int r0 = w*16 + lr, r1 = r0 + 8;
            #pragma unroll
            for (int nt = 0; nt < 8; ++nt) {
                int cc = nt*8 + lc2;
                if (cc     > r0) st[nt][0] = -1e30f;
                if (cc + 1 > r0) st[nt][1] = -1e30f;
                if (cc     > r1) st[nt][2] = -1e30f;
                if (cc + 1 > r1) st[nt][3] = -1e30f;
            }
        }

        float mx0 = -1e30f, mx1 = -1e30f;
        #pragma unroll
        for (int nt = 0; nt < 8; ++nt) {
            mx0 = fmaxf(mx0, fmaxf(st[nt][0], st[nt][1]));
            mx1 = fmaxf(mx1, fmaxf(st[nt][2], st[nt][3]));
        }
        mx0 = fmaxf(mx0, __shfl_xor_sync(0xffffffffu, mx0, 1));
        mx0 = fmaxf(mx0, __shfl_xor_sync(0xffffffffu, mx0, 2));
        mx1 = fmaxf(mx1, __shfl_xor_sync(0xffffffffu, mx1, 1));
        mx1 = fmaxf(mx1, __shfl_xor_sync(0xffffffffu, mx1, 2));
        float mn0 = fmaxf(m0, mx0), mn1 = fmaxf(m1, mx1);
        float a0 = __expf(m0 - mn0), a1 = __expf(m1 - mn1);
        float s0 = 0.f, s1 = 0.f;
        #pragma unroll
        for (int nt = 0; nt < 8; ++nt) {
            st[nt][0] = __expf(st[nt][0] - mn0);
            st[nt][1] = __expf(st[nt][1] - mn0);
            st[nt][2] = __expf(st[nt][2] - mn1);
            st[nt][3] = __expf(st[nt][3] - mn1);
            s0 += st[nt][0] + st[nt][1];
            s1 += st[nt][2] + st[nt][3];
        }
        s0 += __shfl_xor_sync(0xffffffffu, s0, 1);
        s0 += __shfl_xor_sync(0xffffffffu, s0, 2);
        s1 += __shfl_xor_sync(0xffffffffu, s1, 1);
        s1 += __shfl_xor_sync(0xffffffffu, s1, 2);
        l0 = l0 * a0 + s0; l1 = l1 * a1 + s1;
        m0 = mn0; m1 = mn1;
        #pragma unroll
        for (int nt = 0; nt < 8; ++nt) {
            o[nt][0] *= a0; o[nt][1] *= a0; o[nt][2] *= a1; o[nt][3] *= a1;
        }

        unsigned ph[4][4], pl[4][4];
        #pragma unroll
        for (int t = 0; t < 4; ++t) {
            splitp(st[2*t][0],   st[2*t][1],   ph[t][0], pl[t][0]);
            splitp(st[2*t][2],   st[2*t][3],   ph[t][1], pl[t][1]);
            splitp(st[2*t+1][0], st[2*t+1][1], ph[t][2], pl[t][2]);
            splitp(st[2*t+1][2], st[2*t+1][3], ph[t][3], pl[t][3]);
        }
        #pragma unroll
        for (int t = 0; t < 4; ++t) {
            #pragma unroll
            for (int nb = 0; nb < 4; ++nb) {
                unsigned vh[4], vl[4];
                unsigned vo = (unsigned)(((t*16 + (lane&15))*LDB + nb*16 + (lane>>4)*8) * 2);
                ldsm4t(sb + AT_VH(buf) + vo, vh);
                ldsm4t(sb + AT_VL(buf) + vo, vl);
                float* c0 = o[nb*2]; float* c1 = o[nb*2+1];
                mma16816(c0, ph[t], vh[0], vh[1]);
                mma16816(c0, ph[t], vl[0], vl[1]);
                mma16816(c0, pl[t], vh[0], vh[1]);
                mma16816(c1, ph[t], vh[2], vh[3]);
                mma16816(c1, ph[t], vl[2], vl[3]);
                mma16816(c1, pl[t], vh[2], vh[3]);
            }
        }
        buf ^= 1;
    }

    const int rloc = w*16 + lr;
    if (nch == 1) {
        float i0 = 1.f / l0, i1 = 1.f / l1;
        size_t gr0 = (size_t)(b*TT + t0 + rloc);
        #pragma unroll
        for (int nt = 0; nt < 8; ++nt) {
            int col = nt*8 + lc2;
            *(float2*)&out[gr0*HS + col]     = make_float2(o[nt][0]*i0, o[nt][1]*i0);
            *(float2*)&out[(gr0+8)*HS + col] = make_float2(o[nt][2]*i1, o[nt][3]*i1);
        }
    } else {
        size_t slot = (size_t)(b*NQT + qt)*MAXC + c;
        float* Op = gOp + slot*(64*HS);
        #pragma unroll
        for (int nt = 0; nt < 8; ++nt) {
            int col = nt*8 + lc2;
            *(float2*)&Op[rloc*HS + col]     = make_float2(o[nt][0], o[nt][1]);
            *(float2*)&Op[(rloc+8)*HS + col] = make_float2(o[nt][2], o[nt][3]);
        }
        if ((lane & 3) == 0) {
            gM[slot*64 + rloc] = m0;     gL[slot*64 + rloc] = l0;
            gM[slot*64 + rloc + 8] = m1; gL[slot*64 + rloc + 8] = l1;
        }
    }
}

// ---------------------------------------------------------------------------
// Merge split-K partials; grid (NQT-CHK, BB, 4): block z handles 16 cols.
// ---------------------------------------------------------------------------
__global__ __launch_bounds__(256) void merge_kernel(float* __restrict__ out)
{
    const int qt = CHK + blockIdx.x;
    const int b  = blockIdx.y;
    const int z  = blockIdx.z;
    const int nch = (qt >> 3) + 1;
    const int tid = threadIdx.x;
    const int row = tid >> 2;
    const int col = z*16 + (tid & 3) * 4;
    const size_t slot0 = (size_t)(b*NQT + qt)*MAXC;

    float ms = -1e30f;
    float mv[MAXC];
    #pragma unroll
    for (int c = 0; c < MAXC; ++c)
        if (c < nch) { mv[c] = gM[(slot0 + c)*64 + row]; ms = fmaxf(ms, mv[c]); }
    float lsum = 0.f;
    float sc[MAXC];
    #pragma unroll
    for (int c = 0; c < MAXC; ++c)
        if (c < nch) {
            sc[c] = __expf(mv[c] - ms);
            lsum += gL[(slot0 + c)*64 + row] * sc[c];
        }
    float inv = 1.f / lsum;

    float4 acc = make_float4(0.f, 0.f, 0.f, 0.f);
    #pragma unroll
    for (int c = 0; c < MAXC; ++c)
        if (c < nch) {
            float4 v = *(const float4*)&gOp[(slot0 + c)*(64*HS) + row*HS + col];
            acc.x += v.x * sc[c]; acc.y += v.y * sc[c];
            acc.z += v.z * sc[c]; acc.w += v.w * sc[c];
        }
    acc.x *= inv; acc.y *= inv; acc.z *= inv; acc.w *= inv;
    *(float4*)&out[(size_t)(b*TT + qt*64 + row)*HS + col] = acc;
}

// ---------------------------------------------------------------------------
extern "C" void kernel_launch(void* const* d_in, const int* in_sizes, int n_in,
                              void* d_out, int out_size)
{
    const float* x  = (const float*)d_in[0];
    const float* Wq = (const float*)d_in[1];
    const float* Wk = (const float*)d_in[2];
    const float* Wv = (const float*)d_in[3];
    float* out = (float*)d_out;
    (void)in_sizes; (void)n_in; (void)out_size;

    cudaFuncSetAttribute(proj_kernel, cudaFuncAttributeMaxDynamicSharedMemorySize, PROJ_SMEM);
    cudaFuncSetAttribute(attn_kernel, cudaFuncAttributeMaxDynamicSharedMemorySize, ATTN_SMEM);

    splitw_kernel<<<NEMB*HS/1024, 256>>>(Wq, Wk, Wv);
    proj_kernel<<<BT/128, 512, PROJ_SMEM>>>(x);
    attn_kernel<<<dim3(MAXC, NQT, BB), 128, ATTN_SMEM>>>(out);
    merge_kernel<<<dim3(NQT - CHK, BB, 4), 256>>>(out);
}

// round 10
// speedup vs baseline: 1.6328x; 1.2351x over previous
#include <cuda_runtime.h>
#include <cuda_bf16.h>
#include <cuda_fp16.h>
#include <cstdint>

#define NEMB 1024
#define HS 64
#define BB 8
#define TT 2048
#define BT (BB*TT)
#define LDB 72          // 16-bit elem row stride for 64-wide tiles (144B)
#define LDX 40          // bf16 row stride for 32-wide X tiles
#define NQT (TT/64)
#define CHK 8
#define MAXC 4
#define LOG2E 1.4426950408889634f

// fp16 storage: Q hi/lo (for 2-term QK), K single (pre-scaled by log2e), V single
__device__ __align__(16) __half gQh[BT*HS];
__device__ __align__(16) __half gQl[BT*HS];
__device__ __align__(16) __half gK [BT*HS];
__device__ __align__(16) __half gV [BT*HS];
// pre-split bf16 weights, [mat][k][n] layout (proj internals stay bf16x3)
__device__ __align__(16) __nv_bfloat16 gWh3[3*NEMB*HS];
__device__ __align__(16) __nv_bfloat16 gWl3[3*NEMB*HS];
__device__ __align__(16) float gOp[BB*NQT*MAXC*64*HS];
__device__ float gM[BB*NQT*MAXC*64];
__device__ float gL[BB*NQT*MAXC*64];

__device__ __forceinline__ unsigned su32(const void* p) {
    return (unsigned)__cvta_generic_to_shared(p);
}
__device__ __forceinline__ void cpa16(unsigned dst, const void* src) {
    asm volatile("cp.async.cg.shared.global [%0], [%1], 16;\n" :: "r"(dst), "l"(src));
}
__device__ __forceinline__ void cpcommit() { asm volatile("cp.async.commit_group;\n"); }
template<int N> __device__ __forceinline__ void cpwait() {
    asm volatile("cp.async.wait_group %0;\n" :: "n"(N));
}
__device__ __forceinline__ void ldsm4(unsigned a, unsigned* r) {
    asm volatile("ldmatrix.sync.aligned.m8n8.x4.shared.b16 {%0,%1,%2,%3},[%4];\n"
                 : "=r"(r[0]), "=r"(r[1]), "=r"(r[2]), "=r"(r[3]) : "r"(a));
}
__device__ __forceinline__ void ldsm4t(unsigned a, unsigned* r) {
    asm volatile("ldmatrix.sync.aligned.m8n8.x4.trans.shared.b16 {%0,%1,%2,%3},[%4];\n"
                 : "=r"(r[0]), "=r"(r[1]), "=r"(r[2]), "=r"(r[3]) : "r"(a));
}
// bf16 mma (projection)
__device__ __forceinline__ void mma16816(float* c, const unsigned* a, unsigned b0, unsigned b1) {
    asm volatile("mma.sync.aligned.m16n8k16.row.col.f32.bf16.bf16.f32 "
                 "{%0,%1,%2,%3},{%4,%5,%6,%7},{%8,%9},{%0,%1,%2,%3};\n"
                 : "+f"(c[0]), "+f"(c[1]), "+f"(c[2]), "+f"(c[3])
                 : "r"(a[0]), "r"(a[1]), "r"(a[2]), "r"(a[3]), "r"(b0), "r"(b1));
}
// fp16 mma (attention)
__device__ __forceinline__ void mmah(float* c, const unsigned* a, unsigned b0, unsigned b1) {
    asm volatile("mma.sync.aligned.m16n8k16.row.col.f32.f16.f16.f32 "
                 "{%0,%1,%2,%3},{%4,%5,%6,%7},{%8,%9},{%0,%1,%2,%3};\n"
                 : "+f"(c[0]), "+f"(c[1]), "+f"(c[2]), "+f"(c[3])
                 : "r"(a[0]), "r"(a[1]), "r"(a[2]), "r"(a[3]), "r"(b0), "r"(b1));
}
__device__ __forceinline__ void splitp(float x, float y, unsigned& h, unsigned& l) {
    __nv_bfloat162 hh = __floats2bfloat162_rn(x, y);
    float2 f = __bfloat1622float2(hh);
    __nv_bfloat162 ll = __floats2bfloat162_rn(x - f.x, y - f.y);
    h = *(unsigned*)&hh; l = *(unsigned*)&ll;
}
__device__ __forceinline__ void split4s(float4 v, __nv_bfloat16* dh, __nv_bfloat16* dl) {
    unsigned h0, l0, h1, l1;
    splitp(v.x, v.y, h0, l0); splitp(v.z, v.w, h1, l1);
    *(uint2*)dh = make_uint2(h0, h1);
    *(uint2*)dl = make_uint2(l0, l1);
}
// fp16 split of a float pair
__device__ __forceinline__ void splitpH(float x, float y, unsigned& h, unsigned& l) {
    __half2 hh = __floats2half2_rn(x, y);
    float2 f = __half22float2(hh);
    __half2 ll = __floats2half2_rn(x - f.x, y - f.y);
    h = *(unsigned*)&hh; l = *(unsigned*)&ll;
}
__device__ __forceinline__ unsigned packh2(float x, float y) {
    __half2 hh = __floats2half2_rn(x, y);
    return *(unsigned*)&hh;
}

// ---------------------------------------------------------------------------
// Pre-split bf16 weights (once).
// ---------------------------------------------------------------------------
__global__ void splitw_kernel(const float* __restrict__ Wq,
                              const float* __restrict__ Wk,
                              const float* __restrict__ Wv)
{
    const float* Wsrc[3] = {Wq, Wk, Wv};
    int off = (blockIdx.x * 256 + threadIdx.x) * 4;
    #pragma unroll
    for (int mat = 0; mat < 3; ++mat) {
        float4 v = *(const float4*)&Wsrc[mat][off];
        split4s(v, &gWh3[mat*NEMB*HS + off], &gWl3[mat*NEMB*HS + off]);
    }
}

// ---------------------------------------------------------------------------
// Projection: 128 rows of X per CTA -> Q,K,V. bf16x3 internally (exact),
// outputs fp16: Q hi/lo, K (x log2e), V.
// ---------------------------------------------------------------------------
#define PJ_BLK 48128
#define PJ_X(s,h)    ((s)*PJ_BLK + (h)*10240)
#define PJ_W(s,slab) ((s)*PJ_BLK + 20480 + (slab)*4608)
static const int PROJ_SMEM = 2*PJ_BLK;   // 96256

__global__ __launch_bounds__(512) void proj_kernel(const float* __restrict__ x)
{
    extern __shared__ char smc[];
    const unsigned sb = su32(smc);
    const int tid = threadIdx.x, lane = tid & 31, wid = tid >> 5;
    const int wm = wid & 7, wn = wid >> 3;
    const int bt0 = blockIdx.x * 128;

    const int xrow0 = tid >> 3, xc0 = (tid & 7) * 4;
    const int xrow1 = (tid + 512) >> 3, xc1 = ((tid + 512) & 7) * 4;

    float acc[3][4][4];
    #pragma unroll
    for (int m = 0; m < 3; ++m)
        #pragma unroll
        for (int t = 0; t < 4; ++t)
            #pragma unroll
            for (int r = 0; r < 4; ++r) acc[m][t][r] = 0.f;

    #pragma unroll
    for (int r = 0; r < 3; ++r) {
        int u = tid + 512*r;
        int slab = u >> 8, rem = u & 255;
        int row = rem >> 3, c16 = rem & 7;
        const __nv_bfloat16* base = (slab & 1) ? gWl3 : gWh3;
        const char* src = (const char*)(base + (size_t)(slab>>1)*NEMB*HS)
                        + ((size_t)row*HS + c16*8) * 2;
        cpa16(sb + PJ_W(0, slab) + row*144 + c16*16, src);
    }
    cpcommit();
    float4 xr0, xr1;
    xr0 = *(const float4*)&x[(size_t)(bt0+xrow0)*NEMB + xc0];
    xr1 = *(const float4*)&x[(size_t)(bt0+xrow1)*NEMB + xc1];
    split4s(xr0, (__nv_bfloat16*)(smc + PJ_X(0,0)) + xrow0*LDX + xc0,
                 (__nv_bfloat16*)(smc + PJ_X(0,1)) + xrow0*LDX + xc0);
    split4s(xr1, (__nv_bfloat16*)(smc + PJ_X(0,0)) + xrow1*LDX + xc1,
                 (__nv_bfloat16*)(smc + PJ_X(0,1)) + xrow1*LDX + xc1);
    xr0 = *(const float4*)&x[(size_t)(bt0+xrow0)*NEMB + 32 + xc0];
    xr1 = *(const float4*)&x[(size_t)(bt0+xrow1)*NEMB + 32 + xc1];

    int buf = 0;
    for (int kt = 0; kt < 32; ++kt) {
        cpwait<0>();
        __syncthreads();
        if (kt < 31) {
            #pragma unroll
            for (int r = 0; r < 3; ++r) {
                int u = tid + 512*r;
                int slab = u >> 8, rem = u & 255;
                int row = rem >> 3, c16 = rem & 7;
                const __nv_bfloat16* base = (slab & 1) ? gWl3 : gWh3;
                const char* src = (const char*)(base + (size_t)(slab>>1)*NEMB*HS)
                                + ((size_t)((kt+1)*32 + row)*HS + c16*8) * 2;
                cpa16(sb + PJ_W(buf^1, slab) + row*144 + c16*16, src);
            }
            cpcommit();
            split4s(xr0, (__nv_bfloat16*)(smc + PJ_X(buf^1,0)) + xrow0*LDX + xc0,
                         (__nv_bfloat16*)(smc + PJ_X(buf^1,1)) + xrow0*LDX + xc0);
            split4s(xr1, (__nv_bfloat16*)(smc + PJ_X(buf^1,0)) + xrow1*LDX + xc1,
                         (__nv_bfloat16*)(smc + PJ_X(buf^1,1)) + xrow1*LDX + xc1);
            if (kt < 30) {
                xr0 = *(const float4*)&x[(size_t)(bt0+xrow0)*NEMB + (kt+2)*32 + xc0];
                xr1 = *(const float4*)&x[(size_t)(bt0+xrow1)*NEMB + (kt+2)*32 + xc1];
            }
        }

        #pragma unroll
        for (int kk = 0; kk < 2; ++kk) {
            unsigned ah[4], al[4];
            unsigned ao = (unsigned)(((wm*16 + (lane&15))*LDX + kk*16 + (lane>>4)*8) * 2);
            ldsm4(sb + PJ_X(buf,0) + ao, ah);
            ldsm4(sb + PJ_X(buf,1) + ao, al);
            #pragma unroll
            for (int mat = 0; mat < 3; ++mat) {
                #pragma unroll
                for (int nb = 0; nb < 2; ++nb) {
                    unsigned bh[4], bl[4];
                    unsigned bo = (unsigned)(((kk*16 + (lane&15))*LDB +
                                              wn*32 + nb*16 + (lane>>4)*8) * 2);
                    ldsm4t(sb + PJ_W(buf, mat*2)     + bo, bh);
                    ldsm4t(sb + PJ_W(buf, mat*2 + 1) + bo, bl);
                    float* c0 = acc[mat][nb*2]; float* c1 = acc[mat][nb*2+1];
                    mma16816(c0, ah, bh[0], bh[1]);
                    mma16816(c0, ah, bl[0], bl[1]);
                    mma16816(c0, al, bh[0], bh[1]);
                    mma16816(c1, ah, bh[2], bh[3]);
                    mma16816(c1, ah, bl[2], bl[3]);
                    mma16816(c1, al, bh[2], bh[3]);
                }
            }
        }
        buf ^= 1;
    }

    const int r0 = bt0 + wm*16 + (lane >> 2);
    #pragma unroll
    for (int nt = 0; nt < 4; ++nt) {
        int col = wn*32 + nt*8 + 2*(lane & 3);
        unsigned h, l;
        // Q: fp16 hi/lo
        splitpH(acc[0][nt][0], acc[0][nt][1], h, l);
        *(unsigned*)&gQh[(size_t)r0*HS + col] = h;
        *(unsigned*)&gQl[(size_t)r0*HS + col] = l;
        splitpH(acc[0][nt][2], acc[0][nt][3], h, l);
        *(unsigned*)&gQh[(size_t)(r0+8)*HS + col] = h;
        *(unsigned*)&gQl[(size_t)(r0+8)*HS + col] = l;
        // K: single fp16, pre-scaled by log2e
        *(unsigned*)&gK[(size_t)r0*HS + col] =
            packh2(acc[1][nt][0]*LOG2E, acc[1][nt][1]*LOG2E);
        *(unsigned*)&gK[(size_t)(r0+8)*HS + col] =
            packh2(acc[1][nt][2]*LOG2E, acc[1][nt][3]*LOG2E);
        // V: single fp16
        *(unsigned*)&gV[(size_t)r0*HS + col] = packh2(acc[2][nt][0], acc[2][nt][1]);
        *(unsigned*)&gV[(size_t)(r0+8)*HS + col] = packh2(acc[2][nt][2], acc[2][nt][3]);
    }
}

// ---------------------------------------------------------------------------
// Flash attention, split-K, fp16: S = Qh·K + Ql·K (2 MMAs), O += P·V (1 MMA).
// Base-2 softmax (K pre-scaled). smem: 2 stages x {K,V} + Q hi/lo = 55296B, occ 4.
// ---------------------------------------------------------------------------
#define AT_K(s) ((s)*18432)
#define AT_V(s) ((s)*18432 + 9216)
#define AT_QH 36864
#define AT_QL 46080
static const int ATTN_SMEM = 55296;

__global__ __launch_bounds__(128, 4) void attn_kernel(float* __restrict__ out)
{
    const int c  = blockIdx.x;
    const int qt = NQT - 1 - blockIdx.y;
    const int b  = blockIdx.z;
    const int nch = (qt >> 3) + 1;
    if (c >= nch) return;
    const int kt0 = c * CHK;
    const int kt1 = min(qt, kt0 + CHK - 1);
    const int t0 = qt * 64;

    extern __shared__ char smc[];
    const unsigned sb = su32(smc);
    const int tid = threadIdx.x, lane = tid & 31, w = tid >> 5;
    const int lr = lane >> 2;
    const int lc2 = 2 * (lane & 3);

    unsigned d16[4];
    #pragma unroll
    for (int r = 0; r < 4; ++r) {
        int u = tid + 128*r;
        d16[r] = (unsigned)((u>>3)*144 + (u&7)*16);
    }

    // prologue: Q hi/lo to fixed slots
    {
        const char* gq = (const char*)gQh + (size_t)(b*TT + t0)*128;
        const char* gl = (const char*)gQl + (size_t)(b*TT + t0)*128;
        #pragma unroll
        for (int r = 0; r < 4; ++r) {
            int u = tid + 128*r;
            cpa16(sb + AT_QH + d16[r], gq + (size_t)u*16);
            cpa16(sb + AT_QL + d16[r], gl + (size_t)u*16);
        }
        cpcommit();
    }
    // K/V(kt0) -> stage0
    {
        size_t gb = (size_t)(b*TT + kt0*64)*128;
        #pragma unroll
        for (int r = 0; r < 4; ++r) {
            int u = tid + 128*r;
            size_t go = gb + (size_t)u*16;
            cpa16(sb + AT_K(0) + d16[r], (const char*)gK + go);
            cpa16(sb + AT_V(0) + d16[r], (const char*)gV + go);
        }
        cpcommit();
    }

    cpwait<1>();
    __syncthreads();
    unsigned qh[4][4], ql[4][4];
    #pragma unroll
    for (int kk = 0; kk < 4; ++kk) {
        unsigned ao = (unsigned)(((w*16 + (lane&15))*LDB + kk*16 + (lane>>4)*8) * 2);
        ldsm4(sb + AT_QH + ao, qh[kk]);
        ldsm4(sb + AT_QL + ao, ql[kk]);
    }

    float o[8][4];
    #pragma unroll
    for (int t = 0; t < 8; ++t)
        #pragma unroll
        for (int r = 0; r < 4; ++r) o[t][r] = 0.f;
    float m0 = -1e30f, m1 = -1e30f, l0 = 0.f, l1 = 0.f;  // l: per-lane partials

    int buf = 0;
    for (int kt = kt0; kt <= kt1; ++kt) {
        cpwait<0>();
        __syncthreads();
        if (kt < kt1) {
            size_t gb = (size_t)(b*TT + (kt+1)*64)*128;
            #pragma unroll
            for (int r = 0; r < 4; ++r) {
                int u = tid + 128*r;
                size_t go = gb + (size_t)u*16;
                cpa16(sb + AT_K(buf^1) + d16[r], (const char*)gK + go);
                cpa16(sb + AT_V(buf^1) + d16[r], (const char*)gV + go);
            }
            cpcommit();
        }

        // S (base-2 logits) = (Qh + Ql) · K'
        float st[8][4];
        #pragma unroll
        for (int t = 0; t < 8; ++t)
            #pragma unroll
            for (int r = 0; r < 4; ++r) st[t][r] = 0.f;
        #pragma unroll
        for (int kk = 0; kk < 4; ++kk) {
            #pragma unroll
            for (int kb = 0; kb < 4; ++kb) {
                unsigned kh[4];
                unsigned ko = (unsigned)(((kb*16 + (lane&15))*LDB + kk*16 + (lane>>4)*8) * 2);
                ldsm4(sb + AT_K(buf) + ko, kh);
                float* c0 = st[kb*2]; float* c1 = st[kb*2+1];
                mmah(c0, qh[kk], kh[0], kh[2]);
                mmah(c0, ql[kk], kh[0], kh[2]);
                mmah(c1, qh[kk], kh[1], kh[3]);
                mmah(c1, ql[kk], kh[1], kh[3]);
            }
        }

        if (kt == qt) {
            int r0 = w*16 + lr, r1 = r0 + 8;
            #pragma unroll
            for (int nt = 0; nt < 8; ++nt) {
                int cc = nt*8 + lc2;
                if (cc     > r0) st[nt][0] = -1e30f;
                if (cc + 1 > r0) st[nt][1] = -1e30f;
                if (cc     > r1) st[nt][2] = -1e30f;
                if (cc + 1 > r1) st[nt][3] = -1e30f;
            }
        }

        // online softmax (base 2); sums stay per-lane (reduced at the end)
        float mx0 = -1e30f, mx1 = -1e30f;
        #pragma unroll
        for (int nt = 0; nt < 8; ++nt) {
            mx0 = fmaxf(mx0, fmaxf(st[nt][0], st[nt][1]));
            mx1 = fmaxf(mx1, fmaxf(st[nt][2], st[nt][3]));
        }
        mx0 = fmaxf(mx0, __shfl_xor_sync(0xffffffffu, mx0, 1));
        mx0 = fmaxf(mx0, __shfl_xor_sync(0xffffffffu, mx0, 2));
        mx1 = fmaxf(mx1, __shfl_xor_sync(0xffffffffu, mx1, 1));
        mx1 = fmaxf(mx1, __shfl_xor_sync(0xffffffffu, mx1, 2));
        float mn0 = fmaxf(m0, mx0), mn1 = fmaxf(m1, mx1);
        float a0 = exp2f(m0 - mn0), a1 = exp2f(m1 - mn1);
        float s0 = 0.f, s1 = 0.f;
        #pragma unroll
        for (int nt = 0; nt < 8; ++nt) {
            st[nt][0] = exp2f(st[nt][0] - mn0);
            st[nt][1] = exp2f(st[nt][1] - mn0);
            st[nt][2] = exp2f(st[nt][2] - mn1);
            st[nt][3] = exp2f(st[nt][3] - mn1);
            s0 += st[nt][0] + st[nt][1];
            s1 += st[nt][2] + st[nt][3];
        }
        l0 = l0 * a0 + s0; l1 = l1 * a1 + s1;
        m0 = mn0; m1 = mn1;
        #pragma unroll
        for (int nt = 0; nt < 8; ++nt) {
            o[nt][0] *= a0; o[nt][1] *= a0; o[nt][2] *= a1; o[nt][3] *= a1;
        }

        // P fragments: single fp16
        unsigned p[4][4];
        #pragma unroll
        for (int t = 0; t < 4; ++t) {
            p[t][0] = packh2(st[2*t][0],   st[2*t][1]);
            p[t][1] = packh2(st[2*t][2],   st[2*t][3]);
            p[t][2] = packh2(st[2*t+1][0], st[2*t+1][1]);
            p[t][3] = packh2(st[2*t+1][2], st[2*t+1][3]);
        }
        // O += P · V (single-term)
        #pragma unroll
        for (int t = 0; t < 4; ++t) {
            #pragma unroll
            for (int nb = 0; nb < 4; ++nb) {
                unsigned vh[4];
                unsigned vo = (unsigned)(((t*16 + (lane&15))*LDB + nb*16 + (lane>>4)*8) * 2);
                ldsm4t(sb + AT_V(buf) + vo, vh);
                mmah(o[nb*2],   p[t], vh[0], vh[1]);
                mmah(o[nb*2+1], p[t], vh[2], vh[3]);
            }
        }
        buf ^= 1;
    }

    // reduce deferred sums across the quad
    l0 += __shfl_xor_sync(0xffffffffu, l0, 1);
    l0 += __shfl_xor_sync(0xffffffffu, l0, 2);
    l1 += __shfl_xor_sync(0xffffffffu, l1, 1);
    l1 += __shfl_xor_sync(0xffffffffu, l1, 2);

    const int rloc = w*16 + lr;
    if (nch == 1) {
        float i0 = 1.f / l0, i1 = 1.f / l1;
        size_t gr0 = (size_t)(b*TT + t0 + rloc);
        #pragma unroll
        for (int nt = 0; nt < 8; ++nt) {
            int col = nt*8 + lc2;
            *(float2*)&out[gr0*HS + col]     = make_float2(o[nt][0]*i0, o[nt][1]*i0);
            *(float2*)&out[(gr0+8)*HS + col] = make_float2(o[nt][2]*i1, o[nt][3]*i1);
        }
    } else {
        size_t slot = (size_t)(b*NQT + qt)*MAXC + c;
        float* Op = gOp + slot*(64*HS);
        #pragma unroll
        for (int nt = 0; nt < 8; ++nt) {
            int col = nt*8 + lc2;
            *(float2*)&Op[rloc*HS + col]     = make_float2(o[nt][0], o[nt][1]);
            *(float2*)&Op[(rloc+8)*HS + col] = make_float2(o[nt][2], o[nt][3]);
        }
        if ((lane & 3) == 0) {
            gM[slot*64 + rloc] = m0;     gL[slot*64 + rloc] = l0;
            gM[slot*64 + rloc + 8] = m1; gL[slot*64 + rloc + 8] = l1;
        }
    }
}

// ---------------------------------------------------------------------------
// Merge split-K partials (base-2 maxes).
// ---------------------------------------------------------------------------
__global__ __launch_bounds__(256) void merge_kernel(float* __restrict__ out)
{
    const int qt = CHK + blockIdx.x;
    const int b  = blockIdx.y;
    const int z  = blockIdx.z;
    const int nch = (qt >> 3) + 1;
    const int tid = threadIdx.x;
    const int row = tid >> 2;
    const int col = z*16 + (tid & 3) * 4;
    const size_t slot0 = (size_t)(b*NQT + qt)*MAXC;

    float ms = -1e30f;
    float mv[MAXC];
    #pragma unroll
    for (int c = 0; c < MAXC; ++c)
        if (c < nch) { mv[c] = gM[(slot0 + c)*64 + row]; ms = fmaxf(ms, mv[c]); }
    float lsum = 0.f;
    float sc[MAXC];
    #pragma unroll
    for (int c = 0; c < MAXC; ++c)
        if (c < nch) {
            sc[c] = exp2f(mv[c] - ms);
            lsum += gL[(slot0 + c)*64 + row] * sc[c];
        }
    float inv = 1.f / lsum;

    float4 acc = make_float4(0.f, 0.f, 0.f, 0.f);
    #pragma unroll
    for (int c = 0; c < MAXC; ++c)
        if (c < nch) {
            float4 v = *(const float4*)&gOp[(slot0 + c)*(64*HS) + row*HS + col];
            acc.x += v.x * sc[c]; acc.y += v.y * sc[c];
            acc.z += v.z * sc[c]; acc.w += v.w * sc[c];
        }
    acc.x *= inv; acc.y *= inv; acc.z *= inv; acc.w *= inv;
    *(float4*)&out[(size_t)(b*TT + qt*64 + row)*HS + col] = acc;
}

// ---------------------------------------------------------------------------
extern "C" void kernel_launch(void* const* d_in, const int* in_sizes, int n_in,
                              void* d_out, int out_size)
{
    const float* x  = (const float*)d_in[0];
    const float* Wq = (const float*)d_in[1];
    const float* Wk = (const float*)d_in[2];
    const float* Wv = (const float*)d_in[3];
    float* out = (float*)d_out;
    (void)in_sizes; (void)n_in; (void)out_size;

    cudaFuncSetAttribute(proj_kernel, cudaFuncAttributeMaxDynamicSharedMemorySize, PROJ_SMEM);
    cudaFuncSetAttribute(attn_kernel, cudaFuncAttributeMaxDynamicSharedMemorySize, ATTN_SMEM);

    splitw_kernel<<<NEMB*HS/1024, 256>>>(Wq, Wk, Wv);
    proj_kernel<<<BT/128, 512, PROJ_SMEM>>>(x);
    attn_kernel<<<dim3(MAXC, NQT, BB), 128, ATTN_SMEM>>>(out);
    merge_kernel<<<dim3(NQT - CHK, BB, 4), 256>>>(out);
}

// round 11
// speedup vs baseline: 2.3193x; 1.4205x over previous
#include <cuda_runtime.h>
#include <cuda_fp16.h>
#include <cstdint>

#define NEMB 1024
#define HS 64
#define BB 8
#define TT 2048
#define BT (BB*TT)
#define LDB 72          // 16-bit elem row stride for 64-wide tiles (144B)
#define LDX 40          // fp16 row stride for 32-wide X tiles
#define NQT (TT/64)
#define CHK 8
#define MAXC 4
#define LOG2E 1.4426950408889634f

// fp16 storage: Q single, K single (pre-scaled by log2e), V single
__device__ __align__(16) __half gQ[BT*HS];
__device__ __align__(16) __half gK[BT*HS];
__device__ __align__(16) __half gV[BT*HS];
// fp16 weights, [mat][k][n]
__device__ __align__(16) __half gW3[3*NEMB*HS];
__device__ __align__(16) float gOp[BB*NQT*MAXC*64*HS];
__device__ float gM[BB*NQT*MAXC*64];
__device__ float gL[BB*NQT*MAXC*64];

__device__ __forceinline__ unsigned su32(const void* p) {
    return (unsigned)__cvta_generic_to_shared(p);
}
__device__ __forceinline__ void cpa16(unsigned dst, const void* src) {
    asm volatile("cp.async.cg.shared.global [%0], [%1], 16;\n" :: "r"(dst), "l"(src));
}
__device__ __forceinline__ void cpcommit() { asm volatile("cp.async.commit_group;\n"); }
template<int N> __device__ __forceinline__ void cpwait() {
    asm volatile("cp.async.wait_group %0;\n" :: "n"(N));
}
__device__ __forceinline__ void ldsm4(unsigned a, unsigned* r) {
    asm volatile("ldmatrix.sync.aligned.m8n8.x4.shared.b16 {%0,%1,%2,%3},[%4];\n"
                 : "=r"(r[0]), "=r"(r[1]), "=r"(r[2]), "=r"(r[3]) : "r"(a));
}
__device__ __forceinline__ void ldsm4t(unsigned a, unsigned* r) {
    asm volatile("ldmatrix.sync.aligned.m8n8.x4.trans.shared.b16 {%0,%1,%2,%3},[%4];\n"
                 : "=r"(r[0]), "=r"(r[1]), "=r"(r[2]), "=r"(r[3]) : "r"(a));
}
// fp16 mma
__device__ __forceinline__ void mmah(float* c, const unsigned* a, unsigned b0, unsigned b1) {
    asm volatile("mma.sync.aligned.m16n8k16.row.col.f32.f16.f16.f32 "
                 "{%0,%1,%2,%3},{%4,%5,%6,%7},{%8,%9},{%0,%1,%2,%3};\n"
                 : "+f"(c[0]), "+f"(c[1]), "+f"(c[2]), "+f"(c[3])
                 : "r"(a[0]), "r"(a[1]), "r"(a[2]), "r"(a[3]), "r"(b0), "r"(b1));
}
__device__ __forceinline__ unsigned packh2(float x, float y) {
    __half2 hh = __floats2half2_rn(x, y);
    return *(unsigned*)&hh;
}
// fp16 hi/lo split of a float pair
__device__ __forceinline__ void splitpH(float x, float y, unsigned& h, unsigned& l) {
    __half2 hh = __floats2half2_rn(x, y);
    float2 f = __half22float2(hh);
    __half2 ll = __floats2half2_rn(x - f.x, y - f.y);
    h = *(unsigned*)&hh; l = *(unsigned*)&ll;
}
__device__ __forceinline__ void split4sH(float4 v, __half* dh, __half* dl) {
    unsigned h0, l0, h1, l1;
    splitpH(v.x, v.y, h0, l0); splitpH(v.z, v.w, h1, l1);
    *(uint2*)dh = make_uint2(h0, h1);
    *(uint2*)dl = make_uint2(l0, l1);
}

// ---------------------------------------------------------------------------
// Convert weights to fp16 (once).
// ---------------------------------------------------------------------------
__global__ void splitw_kernel(const float* __restrict__ Wq,
                              const float* __restrict__ Wk,
                              const float* __restrict__ Wv)
{
    const float* Wsrc[3] = {Wq, Wk, Wv};
    int off = (blockIdx.x * 256 + threadIdx.x) * 4;
    #pragma unroll
    for (int mat = 0; mat < 3; ++mat) {
        float4 v = *(const float4*)&Wsrc[mat][off];
        uint2 p = make_uint2(packh2(v.x, v.y), packh2(v.z, v.w));
        *(uint2*)&gW3[mat*NEMB*HS + off] = p;
    }
}

// ---------------------------------------------------------------------------
// Projection: 128 rows of X per CTA -> Q,K,V.
// fp16 2-term: (Xh + Xl) · W  (X fp16 hi/lo, W single fp16).
// 512 threads = 16 warps: 8 m-groups x 2 n-groups. KT=32, double-buffered.
// smem/stage: X hi/lo 128x40 fp16 (10240B each) + W 3 slabs x 32x72 (4608B).
// ---------------------------------------------------------------------------
#define PJ_BLK 34304
#define PJ_X(s,h)    ((s)*PJ_BLK + (h)*10240)
#define PJ_W(s,mat)  ((s)*PJ_BLK + 20480 + (mat)*4608)
static const int PROJ_SMEM = 2*PJ_BLK;   // 68608

__global__ __launch_bounds__(512) void proj_kernel(const float* __restrict__ x)
{
    extern __shared__ char smc[];
    const unsigned sb = su32(smc);
    const int tid = threadIdx.x, lane = tid & 31, wid = tid >> 5;
    const int wm = wid & 7, wn = wid >> 3;
    const int bt0 = blockIdx.x * 128;

    const int xrow0 = tid >> 3, xc0 = (tid & 7) * 4;
    const int xrow1 = (tid + 512) >> 3, xc1 = ((tid + 512) & 7) * 4;

    float acc[3][4][4];
    #pragma unroll
    for (int m = 0; m < 3; ++m)
        #pragma unroll
        for (int t = 0; t < 4; ++t)
            #pragma unroll
            for (int r = 0; r < 4; ++r) acc[m][t][r] = 0.f;

    // issue W(0): 768 16B-chunks (3 slabs x 256)
    #pragma unroll
    for (int r = 0; r < 2; ++r) {
        int u = tid + 512*r;
        if (u < 768) {
            int mat = u >> 8, rem = u & 255;
            int row = rem >> 3, c16 = rem & 7;
            const char* src = (const char*)(gW3 + (size_t)mat*NEMB*HS)
                            + ((size_t)row*HS + c16*8) * 2;
            cpa16(sb + PJ_W(0, mat) + row*144 + c16*16, src);
        }
    }
    cpcommit();
    float4 xr0, xr1;
    xr0 = *(const float4*)&x[(size_t)(bt0+xrow0)*NEMB + xc0];
    xr1 = *(const float4*)&x[(size_t)(bt0+xrow1)*NEMB + xc1];
    split4sH(xr0, (__half*)(smc + PJ_X(0,0)) + xrow0*LDX + xc0,
                  (__half*)(smc + PJ_X(0,1)) + xrow0*LDX + xc0);
    split4sH(xr1, (__half*)(smc + PJ_X(0,0)) + xrow1*LDX + xc1,
                  (__half*)(smc + PJ_X(0,1)) + xrow1*LDX + xc1);
    xr0 = *(const float4*)&x[(size_t)(bt0+xrow0)*NEMB + 32 + xc0];
    xr1 = *(const float4*)&x[(size_t)(bt0+xrow1)*NEMB + 32 + xc1];

    int buf = 0;
    for (int kt = 0; kt < 32; ++kt) {
        cpwait<0>();
        __syncthreads();
        if (kt < 31) {
            #pragma unroll
            for (int r = 0; r < 2; ++r) {
                int u = tid + 512*r;
                if (u < 768) {
                    int mat = u >> 8, rem = u & 255;
                    int row = rem >> 3, c16 = rem & 7;
                    const char* src = (const char*)(gW3 + (size_t)mat*NEMB*HS)
                                    + ((size_t)((kt+1)*32 + row)*HS + c16*8) * 2;
                    cpa16(sb + PJ_W(buf^1, mat) + row*144 + c16*16, src);
                }
            }
            cpcommit();
            split4sH(xr0, (__half*)(smc + PJ_X(buf^1,0)) + xrow0*LDX + xc0,
                          (__half*)(smc + PJ_X(buf^1,1)) + xrow0*LDX + xc0);
            split4sH(xr1, (__half*)(smc + PJ_X(buf^1,0)) + xrow1*LDX + xc1,
                          (__half*)(smc + PJ_X(buf^1,1)) + xrow1*LDX + xc1);
            if (kt < 30) {
                xr0 = *(const float4*)&x[(size_t)(bt0+xrow0)*NEMB + (kt+2)*32 + xc0];
                xr1 = *(const float4*)&x[(size_t)(bt0+xrow1)*NEMB + (kt+2)*32 + xc1];
            }
        }

        #pragma unroll
        for (int kk = 0; kk < 2; ++kk) {
            unsigned ah[4], al[4];
            unsigned ao = (unsigned)(((wm*16 + (lane&15))*LDX + kk*16 + (lane>>4)*8) * 2);
            ldsm4(sb + PJ_X(buf,0) + ao, ah);
            ldsm4(sb + PJ_X(buf,1) + ao, al);
            #pragma unroll
            for (int mat = 0; mat < 3; ++mat) {
                #pragma unroll
                for (int nb = 0; nb < 2; ++nb) {
                    unsigned bh[4];
                    unsigned bo = (unsigned)(((kk*16 + (lane&15))*LDB +
                                              wn*32 + nb*16 + (lane>>4)*8) * 2);
                    ldsm4t(sb + PJ_W(buf, mat) + bo, bh);
                    float* c0 = acc[mat][nb*2]; float* c1 = acc[mat][nb*2+1];
                    mmah(c0, ah, bh[0], bh[1]);
                    mmah(c0, al, bh[0], bh[1]);
                    mmah(c1, ah, bh[2], bh[3]);
                    mmah(c1, al, bh[2], bh[3]);
                }
            }
        }
        buf ^= 1;
    }

    const int r0 = bt0 + wm*16 + (lane >> 2);
    #pragma unroll
    for (int nt = 0; nt < 4; ++nt) {
        int col = wn*32 + nt*8 + 2*(lane & 3);
        // Q: single fp16
        *(unsigned*)&gQ[(size_t)r0*HS + col]     = packh2(acc[0][nt][0], acc[0][nt][1]);
        *(unsigned*)&gQ[(size_t)(r0+8)*HS + col] = packh2(acc[0][nt][2], acc[0][nt][3]);
        // K: single fp16, pre-scaled by log2e
        *(unsigned*)&gK[(size_t)r0*HS + col] =
            packh2(acc[1][nt][0]*LOG2E, acc[1][nt][1]*LOG2E);
        *(unsigned*)&gK[(size_t)(r0+8)*HS + col] =
            packh2(acc[1][nt][2]*LOG2E, acc[1][nt][3]*LOG2E);
        // V: single fp16
        *(unsigned*)&gV[(size_t)r0*HS + col]     = packh2(acc[2][nt][0], acc[2][nt][1]);
        *(unsigned*)&gV[(size_t)(r0+8)*HS + col] = packh2(acc[2][nt][2], acc[2][nt][3]);
    }
}

// ---------------------------------------------------------------------------
// Flash attention, split-K, fp16: S = Q·K' (1 MMA term), O += P·V (1 term).
// Base-2 softmax (K pre-scaled). smem: 2 stages x {K,V} + Q = 46080B, occ 4.
// ---------------------------------------------------------------------------
#define AT_K(s) ((s)*18432)
#define AT_V(s) ((s)*18432 + 9216)
#define AT_Q 36864
static const int ATTN_SMEM = 46080;

__global__ __launch_bounds__(128, 4) void attn_kernel(float* __restrict__ out)
{
    const int c  = blockIdx.x;
    const int qt = NQT - 1 - blockIdx.y;
    const int b  = blockIdx.z;
    const int nch = (qt >> 3) + 1;
    if (c >= nch) return;
    const int kt0 = c * CHK;
    const int kt1 = min(qt, kt0 + CHK - 1);
    const int t0 = qt * 64;

    extern __shared__ char smc[];
    const unsigned sb = su32(smc);
    const int tid = threadIdx.x, lane = tid & 31, w = tid >> 5;
    const int lr = lane >> 2;
    const int lc2 = 2 * (lane & 3);

    unsigned d16[4];
    #pragma unroll
    for (int r = 0; r < 4; ++r) {
        int u = tid + 128*r;
        d16[r] = (unsigned)((u>>3)*144 + (u&7)*16);
    }

    // prologue: Q
    {
        const char* gq = (const char*)gQ + (size_t)(b*TT + t0)*128;
        #pragma unroll
        for (int r = 0; r < 4; ++r) {
            int u = tid + 128*r;
            cpa16(sb + AT_Q + d16[r], gq + (size_t)u*16);
        }
        cpcommit();
    }
    // K/V(kt0) -> stage0
    {
        size_t gb = (size_t)(b*TT + kt0*64)*128;
        #pragma unroll
        for (int r = 0; r < 4; ++r) {
            int u = tid + 128*r;
            size_t go = gb + (size_t)u*16;
            cpa16(sb + AT_K(0) + d16[r], (const char*)gK + go);
            cpa16(sb + AT_V(0) + d16[r], (const char*)gV + go);
        }
        cpcommit();
    }

    cpwait<1>();
    __syncthreads();
    unsigned qh[4][4];
    #pragma unroll
    for (int kk = 0; kk < 4; ++kk) {
        unsigned ao = (unsigned)(((w*16 + (lane&15))*LDB + kk*16 + (lane>>4)*8) * 2);
        ldsm4(sb + AT_Q + ao, qh[kk]);
    }

    float o[8][4];
    #pragma unroll
    for (int t = 0; t < 8; ++t)
        #pragma unroll
        for (int r = 0; r < 4; ++r) o[t][r] = 0.f;
    float m0 = -1e30f, m1 = -1e30f, l0 = 0.f, l1 = 0.f;  // l: per-lane partials

    int buf = 0;
    for (int kt = kt0; kt <= kt1; ++kt) {
        cpwait<0>();
        __syncthreads();
        if (kt < kt1) {
            size_t gb = (size_t)(b*TT + (kt+1)*64)*128;
            #pragma unroll
            for (int r = 0; r < 4; ++r) {
                int u = tid + 128*r;
                size_t go = gb + (size_t)u*16;
                cpa16(sb + AT_K(buf^1) + d16[r], (const char*)gK + go);
                cpa16(sb + AT_V(buf^1) + d16[r], (const char*)gV + go);
            }
            cpcommit();
        }

        // S (base-2 logits) = Q · K'
        float st[8][4];
        #pragma unroll
        for (int t = 0; t < 8; ++t)
            #pragma unroll
            for (int r = 0; r < 4; ++r) st[t][r] = 0.f;
        #pragma unroll
        for (int kk = 0; kk < 4; ++kk) {
            #pragma unroll
            for (int kb = 0; kb < 4; ++kb) {
                unsigned kh[4];
                unsigned ko = (unsigned)(((kb*16 + (lane&15))*LDB + kk*16 + (lane>>4)*8) * 2);
                ldsm4(sb + AT_K(buf) + ko, kh);
                mmah(st[kb*2],   qh[kk], kh[0], kh[2]);
                mmah(st[kb*2+1], qh[kk], kh[1], kh[3]);
            }
        }

        if (kt == qt) {
            int r0 = w*16 + lr, r1 = r0 + 8;
            #pragma unroll
            for (int nt = 0; nt < 8; ++nt) {
                int cc = nt*8 + lc2;
                if (cc     > r0) st[nt][0] = -1e30f;
                if (cc + 1 > r0) st[nt][1] = -1e30f;
                if (cc     > r1) st[nt][2] = -1e30f;
                if (cc + 1 > r1) st[nt][3] = -1e30f;
            }
        }

        // online softmax (base 2); sums stay per-lane (reduced at the end)
        float mx0 = -1e30f, mx1 = -1e30f;
        #pragma unroll
        for (int nt = 0; nt < 8; ++nt) {
            mx0 = fmaxf(mx0, fmaxf(st[nt][0], st[nt][1]));
            mx1 = fmaxf(mx1, fmaxf(st[nt][2], st[nt][3]));
        }
        mx0 = fmaxf(mx0, __shfl_xor_sync(0xffffffffu, mx0, 1));
        mx0 = fmaxf(mx0, __shfl_xor_sync(0xffffffffu, mx0, 2));
        mx1 = fmaxf(mx1, __shfl_xor_sync(0xffffffffu, mx1, 1));
        mx1 = fmaxf(mx1, __shfl_xor_sync(0xffffffffu, mx1, 2));
        float mn0 = fmaxf(m0, mx0), mn1 = fmaxf(m1, mx1);
        float a0 = exp2f(m0 - mn0), a1 = exp2f(m1 - mn1);
        float s0 = 0.f, s1 = 0.f;
        #pragma unroll
        for (int nt = 0; nt < 8; ++nt) {
            st[nt][0] = exp2f(st[nt][0] - mn0);
            st[nt][1] = exp2f(st[nt][1] - mn0);
            st[nt][2] = exp2f(st[nt][2] - mn1);
            st[nt][3] = exp2f(st[nt][3] - mn1);
            s0 += st[nt][0] + st[nt][1];
            s1 += st[nt][2] + st[nt][3];
        }
        l0 = l0 * a0 + s0; l1 = l1 * a1 + s1;
        m0 = mn0; m1 = mn1;
        #pragma unroll
        for (int nt = 0; nt < 8; ++nt) {
            o[nt][0] *= a0; o[nt][1] *= a0; o[nt][2] *= a1; o[nt][3] *= a1;
        }

        // P fragments: single fp16
        unsigned p[4][4];
        #pragma unroll
        for (int t = 0; t < 4; ++t) {
            p[t][0] = packh2(st[2*t][0],   st[2*t][1]);
            p[t][1] = packh2(st[2*t][2],   st[2*t][3]);
            p[t][2] = packh2(st[2*t+1][0], st[2*t+1][1]);
            p[t][3] = packh2(st[2*t+1][2], st[2*t+1][3]);
        }
        // O += P · V
        #pragma unroll
        for (int t = 0; t < 4; ++t) {
            #pragma unroll
            for (int nb = 0; nb < 4; ++nb) {
                unsigned vh[4];
                unsigned vo = (unsigned)(((t*16 + (lane&15))*LDB + nb*16 + (lane>>4)*8) * 2);
                ldsm4t(sb + AT_V(buf) + vo, vh);
                mmah(o[nb*2],   p[t], vh[0], vh[1]);
                mmah(o[nb*2+1], p[t], vh[2], vh[3]);
            }
        }
        buf ^= 1;
    }

    // reduce deferred sums across the quad
    l0 += __shfl_xor_sync(0xffffffffu, l0, 1);
    l0 += __shfl_xor_sync(0xffffffffu, l0, 2);
    l1 += __shfl_xor_sync(0xffffffffu, l1, 1);
    l1 += __shfl_xor_sync(0xffffffffu, l1, 2);

    const int rloc = w*16 + lr;
    if (nch == 1) {
        float i0 = 1.f / l0, i1 = 1.f / l1;
        size_t gr0 = (size_t)(b*TT + t0 + rloc);
        #pragma unroll
        for (int nt = 0; nt < 8; ++nt) {
            int col = nt*8 + lc2;
            *(float2*)&out[gr0*HS + col]     = make_float2(o[nt][0]*i0, o[nt][1]*i0);
            *(float2*)&out[(gr0+8)*HS + col] = make_float2(o[nt][2]*i1, o[nt][3]*i1);
        }
    } else {
        size_t slot = (size_t)(b*NQT + qt)*MAXC + c;
        float* Op = gOp + slot*(64*HS);
        #pragma unroll
        for (int nt = 0; nt < 8; ++nt) {
            int col = nt*8 + lc2;
            *(float2*)&Op[rloc*HS + col]     = make_float2(o[nt][0], o[nt][1]);
            *(float2*)&Op[(rloc+8)*HS + col] = make_float2(o[nt][2], o[nt][3]);
        }
        if ((lane & 3) == 0) {
            gM[slot*64 + rloc] = m0;     gL[slot*64 + rloc] = l0;
            gM[slot*64 + rloc + 8] = m1; gL[slot*64 + rloc + 8] = l1;
        }
    }
}

// ---------------------------------------------------------------------------
// Merge split-K partials (base-2 maxes).
// ---------------------------------------------------------------------------
__global__ __launch_bounds__(256) void merge_kernel(float* __restrict__ out)
{
    const int qt = CHK + blockIdx.x;
    const int b  = blockIdx.y;
    const int z  = blockIdx.z;
    const int nch = (qt >> 3) + 1;
    const int tid = threadIdx.x;
    const int row = tid >> 2;
    const int col = z*16 + (tid & 3) * 4;
    const size_t slot0 = (size_t)(b*NQT + qt)*MAXC;

    float ms = -1e30f;
    float mv[MAXC];
    #pragma unroll
    for (int c = 0; c < MAXC; ++c)
        if (c < nch) { mv[c] = gM[(slot0 + c)*64 + row]; ms = fmaxf(ms, mv[c]); }
    float lsum = 0.f;
    float sc[MAXC];
    #pragma unroll
    for (int c = 0; c < MAXC; ++c)
        if (c < nch) {
            sc[c] = exp2f(mv[c] - ms);
            lsum += gL[(slot0 + c)*64 + row] * sc[c];
        }
    float inv = 1.f / lsum;

    float4 acc = make_float4(0.f, 0.f, 0.f, 0.f);
    #pragma unroll
    for (int c = 0; c < MAXC; ++c)
        if (c < nch) {
            float4 v = *(const float4*)&gOp[(slot0 + c)*(64*HS) + row*HS + col];
            acc.x += v.x * sc[c]; acc.y += v.y * sc[c];
            acc.z += v.z * sc[c]; acc.w += v.w * sc[c];
        }
    acc.x *= inv; acc.y *= inv; acc.z *= inv; acc.w *= inv;
    *(float4*)&out[(size_t)(b*TT + qt*64 + row)*HS + col] = acc;
}

// ---------------------------------------------------------------------------
extern "C" void kernel_launch(void* const* d_in, const int* in_sizes, int n_in,
                              void* d_out, int out_size)
{
    const float* x  = (const float*)d_in[0];
    const float* Wq = (const float*)d_in[1];
    const float* Wk = (const float*)d_in[2];
    const float* Wv = (const float*)d_in[3];
    float* out = (float*)d_out;
    (void)in_sizes; (void)n_in; (void)out_size;

    cudaFuncSetAttribute(proj_kernel, cudaFuncAttributeMaxDynamicSharedMemorySize, PROJ_SMEM);
    cudaFuncSetAttribute(attn_kernel, cudaFuncAttributeMaxDynamicSharedMemorySize, ATTN_SMEM);

    splitw_kernel<<<NEMB*HS/1024, 256>>>(Wq, Wk, Wv);
    proj_kernel<<<BT/128, 512, PROJ_SMEM>>>(x);
    attn_kernel<<<dim3(MAXC, NQT, BB), 128, ATTN_SMEM>>>(out);
    merge_kernel<<<dim3(NQT - CHK, BB, 4), 256>>>(out);
}

// round 12
// speedup vs baseline: 2.7946x; 1.2049x over previous
#include <cuda_runtime.h>
#include <cuda_fp16.h>
#include <cstdint>

#define NEMB 1024
#define HS 64
#define BB 8
#define TT 2048
#define BT (BB*TT)
#define LDB 72          // 16-bit elem row stride for 64-wide tiles (144B)
#define LDX 40          // fp16 row stride for 32-wide X tiles
#define NQT (TT/64)
#define CHK 8
#define MAXC 4
#define LOG2E 1.4426950408889634f

// fp16 storage: Q single, K single (pre-scaled by log2e), V single
__device__ __align__(16) __half gQ[BT*HS];
__device__ __align__(16) __half gK[BT*HS];
__device__ __align__(16) __half gV[BT*HS];
// fp16 weights, [mat][k][n]
__device__ __align__(16) __half gW3[3*NEMB*HS];
// split-K partials: O as fp16, m/l fp32
__device__ __align__(16) __half gOp[BB*NQT*MAXC*64*HS];
__device__ float gM[BB*NQT*MAXC*64];
__device__ float gL[BB*NQT*MAXC*64];

__device__ __forceinline__ unsigned su32(const void* p) {
    return (unsigned)__cvta_generic_to_shared(p);
}
__device__ __forceinline__ void cpa16(unsigned dst, const void* src) {
    asm volatile("cp.async.cg.shared.global [%0], [%1], 16;\n" :: "r"(dst), "l"(src));
}
__device__ __forceinline__ void cpcommit() { asm volatile("cp.async.commit_group;\n"); }
template<int N> __device__ __forceinline__ void cpwait() {
    asm volatile("cp.async.wait_group %0;\n" :: "n"(N));
}
__device__ __forceinline__ void ldsm4(unsigned a, unsigned* r) {
    asm volatile("ldmatrix.sync.aligned.m8n8.x4.shared.b16 {%0,%1,%2,%3},[%4];\n"
                 : "=r"(r[0]), "=r"(r[1]), "=r"(r[2]), "=r"(r[3]) : "r"(a));
}
__device__ __forceinline__ void ldsm4t(unsigned a, unsigned* r) {
    asm volatile("ldmatrix.sync.aligned.m8n8.x4.trans.shared.b16 {%0,%1,%2,%3},[%4];\n"
                 : "=r"(r[0]), "=r"(r[1]), "=r"(r[2]), "=r"(r[3]) : "r"(a));
}
__device__ __forceinline__ void mmah(float* c, const unsigned* a, unsigned b0, unsigned b1) {
    asm volatile("mma.sync.aligned.m16n8k16.row.col.f32.f16.f16.f32 "
                 "{%0,%1,%2,%3},{%4,%5,%6,%7},{%8,%9},{%0,%1,%2,%3};\n"
                 : "+f"(c[0]), "+f"(c[1]), "+f"(c[2]), "+f"(c[3])
                 : "r"(a[0]), "r"(a[1]), "r"(a[2]), "r"(a[3]), "r"(b0), "r"(b1));
}
__device__ __forceinline__ unsigned packh2(float x, float y) {
    __half2 hh = __floats2half2_rn(x, y);
    return *(unsigned*)&hh;
}

// ---------------------------------------------------------------------------
// Convert weights to fp16 (once).
// ---------------------------------------------------------------------------
__global__ void splitw_kernel(const float* __restrict__ Wq,
                              const float* __restrict__ Wk,
                              const float* __restrict__ Wv)
{
    const float* Wsrc[3] = {Wq, Wk, Wv};
    int off = (blockIdx.x * 256 + threadIdx.x) * 4;
    #pragma unroll
    for (int mat = 0; mat < 3; ++mat) {
        float4 v = *(const float4*)&Wsrc[mat][off];
        uint2 p = make_uint2(packh2(v.x, v.y), packh2(v.z, v.w));
        *(uint2*)&gW3[mat*NEMB*HS + off] = p;
    }
}

// ---------------------------------------------------------------------------
// Projection: 128 rows of X per CTA -> Q,K,V. Single-term fp16: X·W.
// 512 threads = 16 warps: 8 m-groups x 2 n-groups. KT=32, double-buffered.
// smem/stage: X 128x40 fp16 (10240B) + W 3 slabs x 32x72 (4608B) = 24064.
// ---------------------------------------------------------------------------
#define PJ_BLK 24064
#define PJ_X(s)      ((s)*PJ_BLK)
#define PJ_W(s,mat)  ((s)*PJ_BLK + 10240 + (mat)*4608)
static const int PROJ_SMEM = 2*PJ_BLK;   // 48128

__global__ __launch_bounds__(512) void proj_kernel(const float* __restrict__ x)
{
    extern __shared__ char smc[];
    const unsigned sb = su32(smc);
    const int tid = threadIdx.x, lane = tid & 31, wid = tid >> 5;
    const int wm = wid & 7, wn = wid >> 3;
    const int bt0 = blockIdx.x * 128;

    const int xrow0 = tid >> 3, xc0 = (tid & 7) * 4;
    const int xrow1 = (tid + 512) >> 3, xc1 = ((tid + 512) & 7) * 4;

    float acc[3][4][4];
    #pragma unroll
    for (int m = 0; m < 3; ++m)
        #pragma unroll
        for (int t = 0; t < 4; ++t)
            #pragma unroll
            for (int r = 0; r < 4; ++r) acc[m][t][r] = 0.f;

    // issue W(0): 768 16B-chunks (3 slabs x 256)
    #pragma unroll
    for (int r = 0; r < 2; ++r) {
        int u = tid + 512*r;
        if (u < 768) {
            int mat = u >> 8, rem = u & 255;
            int row = rem >> 3, c16 = rem & 7;
            const char* src = (const char*)(gW3 + (size_t)mat*NEMB*HS)
                            + ((size_t)row*HS + c16*8) * 2;
            cpa16(sb + PJ_W(0, mat) + row*144 + c16*16, src);
        }
    }
    cpcommit();
    float4 xr0, xr1;
    xr0 = *(const float4*)&x[(size_t)(bt0+xrow0)*NEMB + xc0];
    xr1 = *(const float4*)&x[(size_t)(bt0+xrow1)*NEMB + xc1];
    *(uint2*)((__half*)(smc + PJ_X(0)) + xrow0*LDX + xc0) =
        make_uint2(packh2(xr0.x, xr0.y), packh2(xr0.z, xr0.w));
    *(uint2*)((__half*)(smc + PJ_X(0)) + xrow1*LDX + xc1) =
        make_uint2(packh2(xr1.x, xr1.y), packh2(xr1.z, xr1.w));
    xr0 = *(const float4*)&x[(size_t)(bt0+xrow0)*NEMB + 32 + xc0];
    xr1 = *(const float4*)&x[(size_t)(bt0+xrow1)*NEMB + 32 + xc1];

    int buf = 0;
    for (int kt = 0; kt < 32; ++kt) {
        cpwait<0>();
        __syncthreads();
        if (kt < 31) {
            #pragma unroll
            for (int r = 0; r < 2; ++r) {
                int u = tid + 512*r;
                if (u < 768) {
                    int mat = u >> 8, rem = u & 255;
                    int row = rem >> 3, c16 = rem & 7;
                    const char* src = (const char*)(gW3 + (size_t)mat*NEMB*HS)
                                    + ((size_t)((kt+1)*32 + row)*HS + c16*8) * 2;
                    cpa16(sb + PJ_W(buf^1, mat) + row*144 + c16*16, src);
                }
            }
            cpcommit();
            *(uint2*)((__half*)(smc + PJ_X(buf^1)) + xrow0*LDX + xc0) =
                make_uint2(packh2(xr0.x, xr0.y), packh2(xr0.z, xr0.w));
            *(uint2*)((__half*)(smc + PJ_X(buf^1)) + xrow1*LDX + xc1) =
                make_uint2(packh2(xr1.x, xr1.y), packh2(xr1.z, xr1.w));
            if (kt < 30) {
                xr0 = *(const float4*)&x[(size_t)(bt0+xrow0)*NEMB + (kt+2)*32 + xc0];
                xr1 = *(const float4*)&x[(size_t)(bt0+xrow1)*NEMB + (kt+2)*32 + xc1];
            }
        }

        #pragma unroll
        for (int kk = 0; kk < 2; ++kk) {
            unsigned ah[4];
            unsigned ao = (unsigned)(((wm*16 + (lane&15))*LDX + kk*16 + (lane>>4)*8) * 2);
            ldsm4(sb + PJ_X(buf) + ao, ah);
            #pragma unroll
            for (int mat = 0; mat < 3; ++mat) {
                #pragma unroll
                for (int nb = 0; nb < 2; ++nb) {
                    unsigned bh[4];
                    unsigned bo = (unsigned)(((kk*16 + (lane&15))*LDB +
                                              wn*32 + nb*16 + (lane>>4)*8) * 2);
                    ldsm4t(sb + PJ_W(buf, mat) + bo, bh);
                    mmah(acc[mat][nb*2],   ah, bh[0], bh[1]);
                    mmah(acc[mat][nb*2+1], ah, bh[2], bh[3]);
                }
            }
        }
        buf ^= 1;
    }

    const int r0 = bt0 + wm*16 + (lane >> 2);
    #pragma unroll
    for (int nt = 0; nt < 4; ++nt) {
        int col = wn*32 + nt*8 + 2*(lane & 3);
        *(unsigned*)&gQ[(size_t)r0*HS + col]     = packh2(acc[0][nt][0], acc[0][nt][1]);
        *(unsigned*)&gQ[(size_t)(r0+8)*HS + col] = packh2(acc[0][nt][2], acc[0][nt][3]);
        *(unsigned*)&gK[(size_t)r0*HS + col] =
            packh2(acc[1][nt][0]*LOG2E, acc[1][nt][1]*LOG2E);
        *(unsigned*)&gK[(size_t)(r0+8)*HS + col] =
            packh2(acc[1][nt][2]*LOG2E, acc[1][nt][3]*LOG2E);
        *(unsigned*)&gV[(size_t)r0*HS + col]     = packh2(acc[2][nt][0], acc[2][nt][1]);
        *(unsigned*)&gV[(size_t)(r0+8)*HS + col] = packh2(acc[2][nt][2], acc[2][nt][3]);
    }
}

// ---------------------------------------------------------------------------
// Flash attention, split-K, fp16 single-term S and PV. Base-2 softmax.
// smem: 2 stages x {K,V} + Q = 46080B, occ 4.
// ---------------------------------------------------------------------------
#define AT_K(s) ((s)*18432)
#define AT_V(s) ((s)*18432 + 9216)
#define AT_Q 36864
static const int ATTN_SMEM = 46080;

__global__ __launch_bounds__(128, 4) void attn_kernel(float* __restrict__ out)
{
    const int c  = blockIdx.x;
    const int qt = NQT - 1 - blockIdx.y;
    const int b  = blockIdx.z;
    const int nch = (qt >> 3) + 1;
    if (c >= nch) return;
    const int kt0 = c * CHK;
    const int kt1 = min(qt, kt0 + CHK - 1);
    const int t0 = qt * 64;

    extern __shared__ char smc[];
    const unsigned sb = su32(smc);
    const int tid = threadIdx.x, lane = tid & 31, w = tid >> 5;
    const int lr = lane >> 2;
    const int lc2 = 2 * (lane & 3);

    unsigned d16[4];
    #pragma unroll
    for (int r = 0; r < 4; ++r) {
        int u = tid + 128*r;
        d16[r] = (unsigned)((u>>3)*144 + (u&7)*16);
    }

    {
        const char* gq = (const char*)gQ + (size_t)(b*TT + t0)*128;
        #pragma unroll
        for (int r = 0; r < 4; ++r) {
            int u = tid + 128*r;
            cpa16(sb + AT_Q + d16[r], gq + (size_t)u*16);
        }
        cpcommit();
    }
    {
        size_t gb = (size_t)(b*TT + kt0*64)*128;
        #pragma unroll
        for (int r = 0; r < 4; ++r) {
            int u = tid + 128*r;
            size_t go = gb + (size_t)u*16;
            cpa16(sb + AT_K(0) + d16[r], (const char*)gK + go);
            cpa16(sb + AT_V(0) + d16[r], (const char*)gV + go);
        }
        cpcommit();
    }

    cpwait<1>();
    __syncthreads();
    unsigned qh[4][4];
    #pragma unroll
    for (int kk = 0; kk < 4; ++kk) {
        unsigned ao = (unsigned)(((w*16 + (lane&15))*LDB + kk*16 + (lane>>4)*8) * 2);
        ldsm4(sb + AT_Q + ao, qh[kk]);
    }

    float o[8][4];
    #pragma unroll
    for (int t = 0; t < 8; ++t)
        #pragma unroll
        for (int r = 0; r < 4; ++r) o[t][r] = 0.f;
    float m0 = -1e30f, m1 = -1e30f, l0 = 0.f, l1 = 0.f;

    int buf = 0;
    for (int kt = kt0; kt <= kt1; ++kt) {
        cpwait<0>();
        __syncthreads();
        if (kt < kt1) {
            size_t gb = (size_t)(b*TT + (kt+1)*64)*128;
            #pragma unroll
            for (int r = 0; r < 4; ++r) {
                int u = tid + 128*r;
                size_t go = gb + (size_t)u*16;
                cpa16(sb + AT_K(buf^1) + d16[r], (const char*)gK + go);
                cpa16(sb + AT_V(buf^1) + d16[r], (const char*)gV + go);
            }
            cpcommit();
        }

        float st[8][4];
        #pragma unroll
        for (int t = 0; t < 8; ++t)
            #pragma unroll
            for (int r = 0; r < 4; ++r) st[t][r] = 0.f;
        #pragma unroll
        for (int kk = 0; kk < 4; ++kk) {
            #pragma unroll
            for (int kb = 0; kb < 4; ++kb) {
                unsigned kh[4];
                unsigned ko = (unsigned)(((kb*16 + (lane&15))*LDB + kk*16 + (lane>>4)*8) * 2);
                ldsm4(sb + AT_K(buf) + ko, kh);
                mmah(st[kb*2],   qh[kk], kh[0], kh[2]);
                mmah(st[kb*2+1], qh[kk], kh[1], kh[3]);
            }
        }

        if (kt == qt) {
            int r0 = w*16 + lr, r1 = r0 + 8;
            #pragma unroll
            for (int nt = 0; nt < 8; ++nt) {
                int cc = nt*8 + lc2;
                if (cc     > r0) st[nt][0] = -1e30f;
                if (cc + 1 > r0) st[nt][1] = -1e30f;
                if (cc     > r1) st[nt][2] = -1e30f;
                if (cc + 1 > r1) st[nt][3] = -1e30f;
            }
        }

        float mx0 = -1e30f, mx1 = -1e30f;
        #pragma unroll
        for (int nt = 0; nt < 8; ++nt) {
            mx0 = fmaxf(mx0, fmaxf(st[nt][0], st[nt][1]));
            mx1 = fmaxf(mx1, fmaxf(st[nt][2], st[nt][3]));
        }
        mx0 = fmaxf(mx0, __shfl_xor_sync(0xffffffffu, mx0, 1));
        mx0 = fmaxf(mx0, __shfl_xor_sync(0xffffffffu, mx0, 2));
        mx1 = fmaxf(mx1, __shfl_xor_sync(0xffffffffu, mx1, 1));
        mx1 = fmaxf(mx1, __shfl_xor_sync(0xffffffffu, mx1, 2));
        float mn0 = fmaxf(m0, mx0), mn1 = fmaxf(m1, mx1);
        float a0 = exp2f(m0 - mn0), a1 = exp2f(m1 - mn1);
        float s0 = 0.f, s1 = 0.f;
        #pragma unroll
        for (int nt = 0; nt < 8; ++nt) {
            st[nt][0] = exp2f(st[nt][0] - mn0);
            st[nt][1] = exp2f(st[nt][1] - mn0);
            st[nt][2] = exp2f(st[nt][2] - mn1);
            st[nt][3] = exp2f(st[nt][3] - mn1);
            s0 += st[nt][0] + st[nt][1];
            s1 += st[nt][2] + st[nt][3];
        }
        l0 = l0 * a0 + s0; l1 = l1 * a1 + s1;
        m0 = mn0; m1 = mn1;
        #pragma unroll
        for (int nt = 0; nt < 8; ++nt) {
            o[nt][0] *= a0; o[nt][1] *= a0; o[nt][2] *= a1; o[nt][3] *= a1;
        }

        unsigned p[4][4];
        #pragma unroll
        for (int t = 0; t < 4; ++t) {
            p[t][0] = packh2(st[2*t][0],   st[2*t][1]);
            p[t][1] = packh2(st[2*t][2],   st[2*t][3]);
            p[t][2] = packh2(st[2*t+1][0], st[2*t+1][1]);
            p[t][3] = packh2(st[2*t+1][2], st[2*t+1][3]);
        }
        #pragma unroll
        for (int t = 0; t < 4; ++t) {
            #pragma unroll
            for (int nb = 0; nb < 4; ++nb) {
                unsigned vh[4];
                unsigned vo = (unsigned)(((t*16 + (lane&15))*LDB + nb*16 + (lane>>4)*8) * 2);
                ldsm4t(sb + AT_V(buf) + vo, vh);
                mmah(o[nb*2],   p[t], vh[0], vh[1]);
                mmah(o[nb*2+1], p[t], vh[2], vh[3]);
            }
        }
        buf ^= 1;
    }

    l0 += __shfl_xor_sync(0xffffffffu, l0, 1);
    l0 += __shfl_xor_sync(0xffffffffu, l0, 2);
    l1 += __shfl_xor_sync(0xffffffffu, l1, 1);
    l1 += __shfl_xor_sync(0xffffffffu, l1, 2);

    const int rloc = w*16 + lr;
    if (nch == 1) {
        float i0 = 1.f / l0, i1 = 1.f / l1;
        size_t gr0 = (size_t)(b*TT + t0 + rloc);
        #pragma unroll
        for (int nt = 0; nt < 8; ++nt) {
            int col = nt*8 + lc2;
            *(float2*)&out[gr0*HS + col]     = make_float2(o[nt][0]*i0, o[nt][1]*i0);
            *(float2*)&out[(gr0+8)*HS + col] = make_float2(o[nt][2]*i1, o[nt][3]*i1);
        }
    } else {
        size_t slot = (size_t)(b*NQT + qt)*MAXC + c;
        __half* Op = gOp + slot*(64*HS);
        #pragma unroll
        for (int nt = 0; nt < 8; ++nt) {
            int col = nt*8 + lc2;
            *(unsigned*)&Op[rloc*HS + col]     = packh2(o[nt][0], o[nt][1]);
            *(unsigned*)&Op[(rloc+8)*HS + col] = packh2(o[nt][2], o[nt][3]);
        }
        if ((lane & 3) == 0) {
            gM[slot*64 + rloc] = m0;     gL[slot*64 + rloc] = l0;
            gM[slot*64 + rloc + 8] = m1; gL[slot*64 + rloc + 8] = l1;
        }
    }
}

// ---------------------------------------------------------------------------
// Merge split-K partials (fp16 partials, base-2 maxes).
// ---------------------------------------------------------------------------
__global__ __launch_bounds__(256) void merge_kernel(float* __restrict__ out)
{
    const int qt = CHK + blockIdx.x;
    const int b  = blockIdx.y;
    const int z  = blockIdx.z;
    const int nch = (qt >> 3) + 1;
    const int tid = threadIdx.x;
    const int row = tid >> 2;
    const int col = z*16 + (tid & 3) * 4;
    const size_t slot0 = (size_t)(b*NQT + qt)*MAXC;

    float ms = -1e30f;
    float mv[MAXC];
    #pragma unroll
    for (int c = 0; c < MAXC; ++c)
        if (c < nch) { mv[c] = gM[(slot0 + c)*64 + row]; ms = fmaxf(ms, mv[c]); }
    float lsum = 0.f;
    float sc[MAXC];
    #pragma unroll
    for (int c = 0; c < MAXC; ++c)
        if (c < nch) {
            sc[c] = exp2f(mv[c] - ms);
            lsum += gL[(slot0 + c)*64 + row] * sc[c];
        }
    float inv = 1.f / lsum;

    float4 acc = make_float4(0.f, 0.f, 0.f, 0.f);
    #pragma unroll
    for (int c = 0; c < MAXC; ++c)
        if (c < nch) {
            uint2 pv = *(const uint2*)&gOp[(slot0 + c)*(64*HS) + row*HS + col];
            float2 v0 = __half22float2(*(__half2*)&pv.x);
            float2 v1 = __half22float2(*(__half2*)&pv.y);
            acc.x += v0.x * sc[c]; acc.y += v0.y * sc[c];
            acc.z += v1.x * sc[c]; acc.w += v1.y * sc[c];
        }
    acc.x *= inv; acc.y *= inv; acc.z *= inv; acc.w *= inv;
    *(float4*)&out[(size_t)(b*TT + qt*64 + row)*HS + col] = acc;
}

// ---------------------------------------------------------------------------
extern "C" void kernel_launch(void* const* d_in, const int* in_sizes, int n_in,
                              void* d_out, int out_size)
{
    const float* x  = (const float*)d_in[0];
    const float* Wq = (const float*)d_in[1];
    const float* Wk = (const float*)d_in[2];
    const float* Wv = (const float*)d_in[3];
    float* out = (float*)d_out;
    (void)in_sizes; (void)n_in; (void)out_size;

    cudaFuncSetAttribute(proj_kernel, cudaFuncAttributeMaxDynamicSharedMemorySize, PROJ_SMEM);
    cudaFuncSetAttribute(attn_kernel, cudaFuncAttributeMaxDynamicSharedMemorySize, ATTN_SMEM);

    splitw_kernel<<<NEMB*HS/1024, 256>>>(Wq, Wk, Wv);
    proj_kernel<<<BT/128, 512, PROJ_SMEM>>>(x);
    attn_kernel<<<dim3(MAXC, NQT, BB), 128, ATTN_SMEM>>>(out);
    merge_kernel<<<dim3(NQT - CHK, BB, 4), 256>>>(out);
}